// round 6
// baseline (speedup 1.0000x reference)
#include <cuda_runtime.h>
#include <cstdint>

#define SEQ  2048
#define WORD 1024
#define EMB  128
#define NH   16

typedef unsigned long long u64;

// ---------------- device scratch (no allocations allowed) ----------------
__device__ float g_Q [NH * SEQ * EMB];   // [h][s][e]
__device__ float g_Kt[NH * EMB * SEQ];   // [h][e][s]  (K transposed)
__device__ float g_V [NH * SEQ * EMB];   // [h][s][e]
__device__ float g_Z [SEQ * NH * EMB];   // [s][h*EMB + e]

// ---------------- f32x2 helpers (Blackwell packed fp32) ----------------
__device__ __forceinline__ u64 dup2(float v) {
    u64 r; asm("mov.b64 %0, {%1, %1};" : "=l"(r) : "f"(v)); return r;
}
__device__ __forceinline__ u64 fma2(u64 a, u64 b, u64 c) {
    u64 d; asm("fma.rn.f32x2 %0, %1, %2, %3;" : "=l"(d) : "l"(a), "l"(b), "l"(c)); return d;
}
__device__ __forceinline__ u64 mul2(u64 a, u64 b) {
    u64 d; asm("mul.rn.f32x2 %0, %1, %2;" : "=l"(d) : "l"(a), "l"(b)); return d;
}
__device__ __forceinline__ float2 unpk(u64 v) {
    float2 f; asm("mov.b64 {%0, %1}, %2;" : "=f"(f.x), "=f"(f.y) : "l"(v)); return f;
}
__device__ __forceinline__ float ex2f_(float x) {
    float y; asm("ex2.approx.ftz.f32 %0, %1;" : "=f"(y) : "f"(x)); return y;
}

// =======================================================================
// Kernel 1: QKV projection. grid (16, 1, 48): z = kind*16 + head
//   C[s][e] = sum_w x[s][w] * W[h][w][e] + b[h][e]
//   kind 0 -> g_Q, 1 -> g_Kt (transposed), 2 -> g_V
// =======================================================================
__global__ __launch_bounds__(256, 2)
void gemm_qkv(const float* __restrict__ x,
              const float* __restrict__ Wq, const float* __restrict__ bq,
              const float* __restrict__ Wk, const float* __restrict__ bk,
              const float* __restrict__ Wv, const float* __restrict__ bv)
{
    __shared__ float As[128 * 16];
    __shared__ float Bs[16 * 128];

    const int tid  = threadIdx.x;
    const int z    = blockIdx.z;
    const int kind = z >> 4;
    const int h    = z & 15;
    const float* Wp = (kind == 0 ? Wq : (kind == 1 ? Wk : Wv)) + h * WORD * EMB;
    const float* bp = (kind == 0 ? bq : (kind == 1 ? bk : bv)) + h * EMB;
    const int row0 = blockIdx.x * 128;
    const int tx = tid & 15, ty = tid >> 4;

    u64 c2[8][4];
#pragma unroll
    for (int m = 0; m < 8; m++)
#pragma unroll
        for (int p = 0; p < 4; p++) c2[m][p] = 0ull;

#pragma unroll 1
    for (int k0 = 0; k0 < WORD; k0 += 16) {
#pragma unroll
        for (int it = 0; it < 2; it++) {
            int idx = tid + it * 256;
            int r  = idx >> 2, c  = (idx & 3) << 2;
            *(float4*)&As[r * 16 + c]    = *(const float4*)&x [(row0 + r) * WORD + k0 + c];
            int rb = idx >> 5, cb = (idx & 31) << 2;
            *(float4*)&Bs[rb * 128 + cb] = *(const float4*)&Wp[(k0 + rb) * EMB + cb];
        }
        __syncthreads();
#pragma unroll
        for (int k = 0; k < 16; k++) {
            const ulonglong2* bpp = (const ulonglong2*)&Bs[k * 128 + tx * 8];
            ulonglong2 bA = bpp[0], bB = bpp[1];
#pragma unroll
            for (int m = 0; m < 8; m++) {
                u64 a2 = dup2(As[(ty * 8 + m) * 16 + k]);
                c2[m][0] = fma2(a2, bA.x, c2[m][0]);
                c2[m][1] = fma2(a2, bA.y, c2[m][1]);
                c2[m][2] = fma2(a2, bB.x, c2[m][2]);
                c2[m][3] = fma2(a2, bB.y, c2[m][3]);
            }
        }
        __syncthreads();
    }

    float bias8[8];
#pragma unroll
    for (int n = 0; n < 8; n++) bias8[n] = bp[tx * 8 + n];

    float c[8][8];
#pragma unroll
    for (int m = 0; m < 8; m++)
#pragma unroll
        for (int p = 0; p < 4; p++) {
            float2 f = unpk(c2[m][p]);
            c[m][2 * p]     = f.x + bias8[2 * p];
            c[m][2 * p + 1] = f.y + bias8[2 * p + 1];
        }

    if (kind != 1) {
        float* C = (kind == 0 ? g_Q : g_V) + h * SEQ * EMB;
#pragma unroll
        for (int m = 0; m < 8; m++) {
            float* dst = &C[(row0 + ty * 8 + m) * EMB + tx * 8];
            *(float4*)dst       = make_float4(c[m][0], c[m][1], c[m][2], c[m][3]);
            *(float4*)(dst + 4) = make_float4(c[m][4], c[m][5], c[m][6], c[m][7]);
        }
    } else {
        float* C = g_Kt + h * EMB * SEQ;   // transposed: Kt[e][s]
#pragma unroll
        for (int n = 0; n < 8; n++) {
            float* dst = &C[(tx * 8 + n) * SEQ + row0 + ty * 8];
            *(float4*)dst       = make_float4(c[0][n], c[1][n], c[2][n], c[3][n]);
            *(float4*)(dst + 4) = make_float4(c[4][n], c[5][n], c[6][n], c[7][n]);
        }
    }
}

// =======================================================================
// Kernel 2: flash attention. grid (SEQ/64, NH), 256 threads.
//   Smem: Qs[64][128] | Kst[128][64] | Vs[64][128] | Ps[64][64] = 112 KB
// =======================================================================
__global__ __launch_bounds__(256, 2)
void attn_kernel()
{
    extern __shared__ float sm[];
    float* Qs  = sm;             // 8192
    float* Kst = sm + 8192;      // 8192  [e][j]
    float* Vs  = sm + 16384;     // 8192  [k][c]
    float* Ps  = sm + 24576;     // 4096  [i][k]

    const int tid = threadIdx.x;
    const int qb  = blockIdx.x * 64;
    const int h   = blockIdx.y;
    const float* Qg  = g_Q  + h * SEQ * EMB;
    const float* Ktg = g_Kt + h * EMB * SEQ;
    const float* Vg  = g_V  + h * SEQ * EMB;

    const int tx = tid & 15, ty = tid >> 4;
    const int i0 = ty * 4;        // 4 score/output rows per thread
    const int j0 = tx * 4;        // 4 score cols
    const int c0 = tx * 8;        // 8 output cols
    const float qscale = 0.1275174405080890f;  // (1/sqrt(128)) * log2(e)

    // load Q tile, pre-scaled into log2 domain
#pragma unroll
    for (int it = 0; it < 8; it++) {
        int idx = tid + it * 256;
        int r = idx >> 5, c = (idx & 31) << 2;
        float4 v = *(const float4*)&Qg[(qb + r) * EMB + c];
        v.x *= qscale; v.y *= qscale; v.z *= qscale; v.w *= qscale;
        *(float4*)&Qs[r * EMB + c] = v;
    }

    u64 acc2[4][4];
#pragma unroll
    for (int i = 0; i < 4; i++)
#pragma unroll
        for (int p = 0; p < 4; p++) acc2[i][p] = 0ull;
    float mrow[4] = {-1e30f, -1e30f, -1e30f, -1e30f};
    float lrow[4] = {0.f, 0.f, 0.f, 0.f};

#pragma unroll 1
    for (int kt = 0; kt < SEQ / 64; kt++) {
        const int kb = kt * 64;
        __syncthreads();   // previous iteration's PV reads done
#pragma unroll
        for (int it = 0; it < 8; it++) {
            int idx = tid + it * 256;
            int e = idx >> 4, j = (idx & 15) << 2;
            *(float4*)&Kst[e * 64 + j] = *(const float4*)&Ktg[e * SEQ + kb + j];
            int r = idx >> 5, c = (idx & 31) << 2;
            *(float4*)&Vs[r * EMB + c] = *(const float4*)&Vg[(kb + r) * EMB + c];
        }
        __syncthreads();

        // ---- S = Qs @ K^T (64x64, log2 domain), f32x2 over j ----
        u64 s2[4][2];
#pragma unroll
        for (int i = 0; i < 4; i++) { s2[i][0] = 0ull; s2[i][1] = 0ull; }
#pragma unroll 4
        for (int e0 = 0; e0 < EMB; e0 += 4) {
            float4 qv[4];
#pragma unroll
            for (int i = 0; i < 4; i++) qv[i] = *(const float4*)&Qs[(i0 + i) * EMB + e0];
            ulonglong2 kv[4];
#pragma unroll
            for (int e = 0; e < 4; e++) kv[e] = *(const ulonglong2*)&Kst[(e0 + e) * 64 + j0];
#pragma unroll
            for (int i = 0; i < 4; i++) {
                const float* qf = (const float*)&qv[i];
#pragma unroll
                for (int e = 0; e < 4; e++) {
                    u64 a2 = dup2(qf[e]);
                    s2[i][0] = fma2(a2, kv[e].x, s2[i][0]);
                    s2[i][1] = fma2(a2, kv[e].y, s2[i][1]);
                }
            }
        }

        // ---- online softmax update (row group = 16 lanes sharing ty) ----
#pragma unroll
        for (int i = 0; i < 4; i++) {
            float2 p01 = unpk(s2[i][0]), p23 = unpk(s2[i][1]);
            float s0 = p01.x, s1 = p01.y, sc2 = p23.x, s3 = p23.y;
            float mx = fmaxf(fmaxf(s0, s1), fmaxf(sc2, s3));
            mx = fmaxf(mx, __shfl_xor_sync(0xffffffffu, mx, 1));
            mx = fmaxf(mx, __shfl_xor_sync(0xffffffffu, mx, 2));
            mx = fmaxf(mx, __shfl_xor_sync(0xffffffffu, mx, 4));
            mx = fmaxf(mx, __shfl_xor_sync(0xffffffffu, mx, 8));
            float mnew  = fmaxf(mrow[i], mx);
            float alpha = ex2f_(mrow[i] - mnew);
            float e0v = ex2f_(s0 - mnew), e1v = ex2f_(s1 - mnew);
            float e2v = ex2f_(sc2 - mnew), e3v = ex2f_(s3 - mnew);
            float rs = (e0v + e1v) + (e2v + e3v);
            rs += __shfl_xor_sync(0xffffffffu, rs, 1);
            rs += __shfl_xor_sync(0xffffffffu, rs, 2);
            rs += __shfl_xor_sync(0xffffffffu, rs, 4);
            rs += __shfl_xor_sync(0xffffffffu, rs, 8);
            lrow[i] = lrow[i] * alpha + rs;
            mrow[i] = mnew;
            u64 al2 = dup2(alpha);
            acc2[i][0] = mul2(al2, acc2[i][0]);
            acc2[i][1] = mul2(al2, acc2[i][1]);
            acc2[i][2] = mul2(al2, acc2[i][2]);
            acc2[i][3] = mul2(al2, acc2[i][3]);
            *(float4*)&Ps[(i0 + i) * 64 + j0] = make_float4(e0v, e1v, e2v, e3v);
        }
        __syncthreads();

        // ---- O += P @ V  (64x128) ----
#pragma unroll 4
        for (int k = 0; k < 64; k++) {
            const ulonglong2* vp = (const ulonglong2*)&Vs[k * EMB + c0];
            ulonglong2 vA = vp[0], vB = vp[1];
#pragma unroll
            for (int i = 0; i < 4; i++) {
                u64 p2 = dup2(Ps[(i0 + i) * 64 + k]);
                acc2[i][0] = fma2(p2, vA.x, acc2[i][0]);
                acc2[i][1] = fma2(p2, vA.y, acc2[i][1]);
                acc2[i][2] = fma2(p2, vB.x, acc2[i][2]);
                acc2[i][3] = fma2(p2, vB.y, acc2[i][3]);
            }
        }
    }

    // ---- epilogue: normalize and write Z[s][h*EMB + e] ----
#pragma unroll
    for (int i = 0; i < 4; i++) {
        float rl = 1.0f / lrow[i];
        float o[8];
#pragma unroll
        for (int p = 0; p < 4; p++) {
            float2 f = unpk(acc2[i][p]);
            o[2 * p]     = f.x * rl;
            o[2 * p + 1] = f.y * rl;
        }
        float* dst = &g_Z[(qb + i0 + i) * (NH * EMB) + h * EMB + c0];
        *(float4*)dst       = make_float4(o[0], o[1], o[2], o[3]);
        *(float4*)(dst + 4) = make_float4(o[4], o[5], o[6], o[7]);
    }
}

// =======================================================================
// Kernel 3: out = Z[2048,2048] @ proj[2048,128]. grid 32, tile 64x128.
// =======================================================================
__global__ __launch_bounds__(256, 2)
void gemm_proj(const float* __restrict__ proj, float* __restrict__ out)
{
    __shared__ float As[64 * 16];
    __shared__ float Bs[16 * 128];

    const int tid = threadIdx.x;
    const int row0 = blockIdx.x * 64;
    const int tx = tid & 15, ty = tid >> 4;
    const int HK = NH * EMB;  // 2048

    u64 c2[4][4];
#pragma unroll
    for (int m = 0; m < 4; m++)
#pragma unroll
        for (int p = 0; p < 4; p++) c2[m][p] = 0ull;

#pragma unroll 1
    for (int k0 = 0; k0 < HK; k0 += 16) {
        {
            int r = tid >> 2, c = (tid & 3) << 2;            // 64x16 -> 256 float4
            *(float4*)&As[r * 16 + c] = *(const float4*)&g_Z[(row0 + r) * HK + k0 + c];
        }
#pragma unroll
        for (int it = 0; it < 2; it++) {
            int idx = tid + it * 256;
            int rb = idx >> 5, cb = (idx & 31) << 2;         // 16x128 -> 512 float4
            *(float4*)&Bs[rb * 128 + cb] = *(const float4*)&proj[(k0 + rb) * EMB + cb];
        }
        __syncthreads();
#pragma unroll
        for (int k = 0; k < 16; k++) {
            const ulonglong2* bpp = (const ulonglong2*)&Bs[k * 128 + tx * 8];
            ulonglong2 bA = bpp[0], bB = bpp[1];
#pragma unroll
            for (int m = 0; m < 4; m++) {
                u64 a2 = dup2(As[(ty * 4 + m) * 16 + k]);
                c2[m][0] = fma2(a2, bA.x, c2[m][0]);
                c2[m][1] = fma2(a2, bA.y, c2[m][1]);
                c2[m][2] = fma2(a2, bB.x, c2[m][2]);
                c2[m][3] = fma2(a2, bB.y, c2[m][3]);
            }
        }
        __syncthreads();
    }

#pragma unroll
    for (int m = 0; m < 4; m++) {
        float o[8];
#pragma unroll
        for (int p = 0; p < 4; p++) {
            float2 f = unpk(c2[m][p]);
            o[2 * p] = f.x; o[2 * p + 1] = f.y;
        }
        float* dst = &out[(row0 + ty * 4 + m) * EMB + tx * 8];
        *(float4*)dst       = make_float4(o[0], o[1], o[2], o[3]);
        *(float4*)(dst + 4) = make_float4(o[4], o[5], o[6], o[7]);
    }
}

// =======================================================================
extern "C" void kernel_launch(void* const* d_in, const int* in_sizes, int n_in,
                              void* d_out, int out_size)
{
    (void)in_sizes; (void)n_in; (void)out_size;
    const float* x    = (const float*)d_in[0];
    const float* Wq   = (const float*)d_in[1];
    const float* bq   = (const float*)d_in[2];
    const float* Wk   = (const float*)d_in[3];
    const float* bk   = (const float*)d_in[4];
    const float* Wv   = (const float*)d_in[5];
    const float* bv   = (const float*)d_in[6];
    const float* proj = (const float*)d_in[7];
    float* out = (float*)d_out;

    static const int SMEM_ATTN = 112 * 1024;
    cudaFuncSetAttribute(attn_kernel, cudaFuncAttributeMaxDynamicSharedMemorySize, SMEM_ATTN);

    dim3 gq(SEQ / 128, 1, 48);
    gemm_qkv<<<gq, 256>>>(x, Wq, bq, Wk, bk, Wv, bv);

    dim3 ga(SEQ / 64, NH);
    attn_kernel<<<ga, 256, SMEM_ATTN>>>();

    gemm_proj<<<SEQ / 64, 256>>>(proj, out);
}

// round 7
// speedup vs baseline: 1.2700x; 1.2700x over previous
#include <cuda_runtime.h>
#include <cstdint>

#define SEQ  2048
#define WORD 1024
#define EMB  128
#define NH   16
#define NSPLIT 8

typedef unsigned long long u64;

// ---------------- device scratch (no allocations allowed) ----------------
__device__ float g_Q [NH * SEQ * EMB];        // [h][s][e]
__device__ float g_Kt[NH * EMB * SEQ];        // [h][e][s]  (K transposed)
__device__ float g_V [NH * SEQ * EMB];        // [h][s][e]
__device__ float g_Z [SEQ * NH * EMB];        // [s][h*EMB + e]
__device__ float g_Pp[NSPLIT * SEQ * EMB];    // proj split-K partials

// ---------------- f32x2 helpers (Blackwell packed fp32) ----------------
__device__ __forceinline__ u64 dup2(float v) {
    u64 r; asm("mov.b64 %0, {%1, %1};" : "=l"(r) : "f"(v)); return r;
}
__device__ __forceinline__ u64 fma2(u64 a, u64 b, u64 c) {
    u64 d; asm("fma.rn.f32x2 %0, %1, %2, %3;" : "=l"(d) : "l"(a), "l"(b), "l"(c)); return d;
}
__device__ __forceinline__ u64 mul2(u64 a, u64 b) {
    u64 d; asm("mul.rn.f32x2 %0, %1, %2;" : "=l"(d) : "l"(a), "l"(b)); return d;
}
__device__ __forceinline__ float2 unpk(u64 v) {
    float2 f; asm("mov.b64 {%0, %1}, %2;" : "=f"(f.x), "=f"(f.y) : "l"(v)); return f;
}
__device__ __forceinline__ float ex2f_(float x) {
    float y; asm("ex2.approx.ftz.f32 %0, %1;" : "=f"(y) : "f"(x)); return y;
}

// =======================================================================
// Kernel 1: QKV projection. grid (16, 1, 48): z = kind*16 + head
//   C[s][e] = sum_w x[s][w] * W[h][w][e] + b[h][e]
//   kind 0 -> g_Q, 1 -> g_Kt (transposed), 2 -> g_V
//   A tile stored TRANSPOSED in smem (As_t[k][r], pad 132) so the inner
//   loop reads A with 2x LDS.128 instead of 8x scalar LDS (smem-wf fix).
// =======================================================================
__global__ __launch_bounds__(256, 2)
void gemm_qkv(const float* __restrict__ x,
              const float* __restrict__ Wq, const float* __restrict__ bq,
              const float* __restrict__ Wk, const float* __restrict__ bk,
              const float* __restrict__ Wv, const float* __restrict__ bv)
{
    __shared__ float As[16 * 132];   // [k][r], padded
    __shared__ float Bs[16 * 128];   // [k][e]

    const int tid  = threadIdx.x;
    const int z    = blockIdx.z;
    const int kind = z >> 4;
    const int h    = z & 15;
    const float* Wp = (kind == 0 ? Wq : (kind == 1 ? Wk : Wv)) + h * WORD * EMB;
    const float* bp = (kind == 0 ? bq : (kind == 1 ? bk : bv)) + h * EMB;
    const int row0 = blockIdx.x * 128;
    const int tx = tid & 15, ty = tid >> 4;

    u64 c2[8][4];
#pragma unroll
    for (int m = 0; m < 8; m++)
#pragma unroll
        for (int p = 0; p < 4; p++) c2[m][p] = 0ull;

#pragma unroll 1
    for (int k0 = 0; k0 < WORD; k0 += 16) {
#pragma unroll
        for (int it = 0; it < 2; it++) {
            int idx = tid + it * 256;
            int r  = idx >> 2, c  = (idx & 3) << 2;
            float4 v = *(const float4*)&x[(row0 + r) * WORD + k0 + c];
            As[(c + 0) * 132 + r] = v.x;
            As[(c + 1) * 132 + r] = v.y;
            As[(c + 2) * 132 + r] = v.z;
            As[(c + 3) * 132 + r] = v.w;
            int rb = idx >> 5, cb = (idx & 31) << 2;
            *(float4*)&Bs[rb * 128 + cb] = *(const float4*)&Wp[(k0 + rb) * EMB + cb];
        }
        __syncthreads();
#pragma unroll
        for (int k = 0; k < 16; k++) {
            const ulonglong2* bpp = (const ulonglong2*)&Bs[k * 128 + tx * 8];
            ulonglong2 bA = bpp[0], bB = bpp[1];
            float4 aA = *(const float4*)&As[k * 132 + ty * 8];
            float4 aB = *(const float4*)&As[k * 132 + ty * 8 + 4];
            const float* afA = (const float*)&aA;
            const float* afB = (const float*)&aB;
#pragma unroll
            for (int m = 0; m < 4; m++) {
                u64 a2 = dup2(afA[m]);
                c2[m][0] = fma2(a2, bA.x, c2[m][0]);
                c2[m][1] = fma2(a2, bA.y, c2[m][1]);
                c2[m][2] = fma2(a2, bB.x, c2[m][2]);
                c2[m][3] = fma2(a2, bB.y, c2[m][3]);
            }
#pragma unroll
            for (int m = 0; m < 4; m++) {
                u64 a2 = dup2(afB[m]);
                c2[m + 4][0] = fma2(a2, bA.x, c2[m + 4][0]);
                c2[m + 4][1] = fma2(a2, bA.y, c2[m + 4][1]);
                c2[m + 4][2] = fma2(a2, bB.x, c2[m + 4][2]);
                c2[m + 4][3] = fma2(a2, bB.y, c2[m + 4][3]);
            }
        }
        __syncthreads();
    }

    float bias8[8];
#pragma unroll
    for (int n = 0; n < 8; n++) bias8[n] = bp[tx * 8 + n];

    float c[8][8];
#pragma unroll
    for (int m = 0; m < 8; m++)
#pragma unroll
        for (int p = 0; p < 4; p++) {
            float2 f = unpk(c2[m][p]);
            c[m][2 * p]     = f.x + bias8[2 * p];
            c[m][2 * p + 1] = f.y + bias8[2 * p + 1];
        }

    if (kind != 1) {
        float* C = (kind == 0 ? g_Q : g_V) + h * SEQ * EMB;
#pragma unroll
        for (int m = 0; m < 8; m++) {
            float* dst = &C[(row0 + ty * 8 + m) * EMB + tx * 8];
            *(float4*)dst       = make_float4(c[m][0], c[m][1], c[m][2], c[m][3]);
            *(float4*)(dst + 4) = make_float4(c[m][4], c[m][5], c[m][6], c[m][7]);
        }
    } else {
        float* C = g_Kt + h * EMB * SEQ;   // transposed: Kt[e][s]
#pragma unroll
        for (int n = 0; n < 8; n++) {
            float* dst = &C[(tx * 8 + n) * SEQ + row0 + ty * 8];
            *(float4*)dst       = make_float4(c[0][n], c[1][n], c[2][n], c[3][n]);
            *(float4*)(dst + 4) = make_float4(c[4][n], c[5][n], c[6][n], c[7][n]);
        }
    }
}

// =======================================================================
// Kernel 2: flash attention v2. grid (SEQ/128, NH), 256 threads, 1 CTA/SM.
//   BQ=128, BK=64. Smem: Qs[128][128] | Kst[128][64] | Vs[64][128] |
//   Ps[128][64]  = 160 KB. Thread tiles: S 8x4, O 8x8 (f32x2 pairs).
//   PV reads P as float4 over 4 k (vectorized broadcast).
// =======================================================================
__global__ __launch_bounds__(256, 1)
void attn_kernel()
{
    extern __shared__ float sm[];
    float* Qs  = sm;              // 16384 floats  [i][e]
    float* Kst = sm + 16384;      //  8192 floats  [e][j]
    float* Vs  = sm + 24576;      //  8192 floats  [k][c]
    float* Ps  = sm + 32768;      //  8192 floats  [i][k]

    const int tid = threadIdx.x;
    const int qb  = blockIdx.x * 128;
    const int h   = blockIdx.y;
    const float* Qg  = g_Q  + h * SEQ * EMB;
    const float* Ktg = g_Kt + h * EMB * SEQ;
    const float* Vg  = g_V  + h * SEQ * EMB;

    const int tx = tid & 15, ty = tid >> 4;
    const int i0 = ty * 8;        // 8 score/output rows per thread
    const int j0 = tx * 4;        // 4 score cols
    const int c0 = tx * 8;        // 8 output cols
    const float qscale = 0.1275174405080890f;  // (1/sqrt(128)) * log2(e)

    // load Q tile (128x128), pre-scaled into log2 domain
#pragma unroll
    for (int it = 0; it < 16; it++) {
        int idx = tid + it * 256;
        int r = idx >> 5, c = (idx & 31) << 2;
        float4 v = *(const float4*)&Qg[(qb + r) * EMB + c];
        v.x *= qscale; v.y *= qscale; v.z *= qscale; v.w *= qscale;
        *(float4*)&Qs[r * EMB + c] = v;
    }

    u64 acc2[8][4];
#pragma unroll
    for (int i = 0; i < 8; i++)
#pragma unroll
        for (int p = 0; p < 4; p++) acc2[i][p] = 0ull;
    float mrow[8], lrow[8];
#pragma unroll
    for (int i = 0; i < 8; i++) { mrow[i] = -1e30f; lrow[i] = 0.f; }

#pragma unroll 1
    for (int kt = 0; kt < SEQ / 64; kt++) {
        const int kb = kt * 64;
        __syncthreads();   // previous iteration's PV reads done with Vs
#pragma unroll
        for (int it = 0; it < 8; it++) {
            int idx = tid + it * 256;
            int e = idx >> 4, j = (idx & 15) << 2;
            *(float4*)&Kst[e * 64 + j] = *(const float4*)&Ktg[e * SEQ + kb + j];
            int r = idx >> 5, c = (idx & 31) << 2;
            *(float4*)&Vs[r * EMB + c] = *(const float4*)&Vg[(kb + r) * EMB + c];
        }
        __syncthreads();

        // ---- S = Qs @ K^T (128x64, log2 domain), f32x2 over j ----
        u64 s2[8][2];
#pragma unroll
        for (int i = 0; i < 8; i++) { s2[i][0] = 0ull; s2[i][1] = 0ull; }
#pragma unroll 2
        for (int e0 = 0; e0 < EMB; e0 += 4) {
            float4 qv[8];
#pragma unroll
            for (int i = 0; i < 8; i++) qv[i] = *(const float4*)&Qs[(i0 + i) * EMB + e0];
            ulonglong2 kv[4];
#pragma unroll
            for (int e = 0; e < 4; e++) kv[e] = *(const ulonglong2*)&Kst[(e0 + e) * 64 + j0];
#pragma unroll
            for (int i = 0; i < 8; i++) {
                const float* qf = (const float*)&qv[i];
#pragma unroll
                for (int e = 0; e < 4; e++) {
                    u64 a2 = dup2(qf[e]);
                    s2[i][0] = fma2(a2, kv[e].x, s2[i][0]);
                    s2[i][1] = fma2(a2, kv[e].y, s2[i][1]);
                }
            }
        }

        // ---- online softmax update (row group = 16 lanes sharing ty) ----
#pragma unroll
        for (int i = 0; i < 8; i++) {
            float2 p01 = unpk(s2[i][0]), p23 = unpk(s2[i][1]);
            float s0 = p01.x, s1 = p01.y, sc2 = p23.x, s3 = p23.y;
            float mx = fmaxf(fmaxf(s0, s1), fmaxf(sc2, s3));
            mx = fmaxf(mx, __shfl_xor_sync(0xffffffffu, mx, 1));
            mx = fmaxf(mx, __shfl_xor_sync(0xffffffffu, mx, 2));
            mx = fmaxf(mx, __shfl_xor_sync(0xffffffffu, mx, 4));
            mx = fmaxf(mx, __shfl_xor_sync(0xffffffffu, mx, 8));
            float mnew  = fmaxf(mrow[i], mx);
            float alpha = ex2f_(mrow[i] - mnew);
            float e0v = ex2f_(s0 - mnew), e1v = ex2f_(s1 - mnew);
            float e2v = ex2f_(sc2 - mnew), e3v = ex2f_(s3 - mnew);
            float rs = (e0v + e1v) + (e2v + e3v);
            rs += __shfl_xor_sync(0xffffffffu, rs, 1);
            rs += __shfl_xor_sync(0xffffffffu, rs, 2);
            rs += __shfl_xor_sync(0xffffffffu, rs, 4);
            rs += __shfl_xor_sync(0xffffffffu, rs, 8);
            lrow[i] = lrow[i] * alpha + rs;
            mrow[i] = mnew;
            u64 al2 = dup2(alpha);
            acc2[i][0] = mul2(al2, acc2[i][0]);
            acc2[i][1] = mul2(al2, acc2[i][1]);
            acc2[i][2] = mul2(al2, acc2[i][2]);
            acc2[i][3] = mul2(al2, acc2[i][3]);
            *(float4*)&Ps[(i0 + i) * 64 + j0] = make_float4(e0v, e1v, e2v, e3v);
        }
        __syncthreads();

        // ---- O += P @ V  (128x128), P loaded float4 over 4 k ----
#pragma unroll 1
        for (int k0 = 0; k0 < 64; k0 += 4) {
            float4 p4[8];
#pragma unroll
            for (int i = 0; i < 8; i++) p4[i] = *(const float4*)&Ps[(i0 + i) * 64 + k0];
#pragma unroll
            for (int kk = 0; kk < 4; kk++) {
                const ulonglong2* vp = (const ulonglong2*)&Vs[(k0 + kk) * EMB + c0];
                ulonglong2 vA = vp[0], vB = vp[1];
#pragma unroll
                for (int i = 0; i < 8; i++) {
                    u64 p2 = dup2(((const float*)&p4[i])[kk]);
                    acc2[i][0] = fma2(p2, vA.x, acc2[i][0]);
                    acc2[i][1] = fma2(p2, vA.y, acc2[i][1]);
                    acc2[i][2] = fma2(p2, vB.x, acc2[i][2]);
                    acc2[i][3] = fma2(p2, vB.y, acc2[i][3]);
                }
            }
        }
    }

    // ---- epilogue: normalize and write Z[s][h*EMB + e] ----
#pragma unroll
    for (int i = 0; i < 8; i++) {
        float rl = 1.0f / lrow[i];
        float o[8];
#pragma unroll
        for (int p = 0; p < 4; p++) {
            float2 f = unpk(acc2[i][p]);
            o[2 * p]     = f.x * rl;
            o[2 * p + 1] = f.y * rl;
        }
        float* dst = &g_Z[(qb + i0 + i) * (NH * EMB) + h * EMB + c0];
        *(float4*)dst       = make_float4(o[0], o[1], o[2], o[3]);
        *(float4*)(dst + 4) = make_float4(o[4], o[5], o[6], o[7]);
    }
}

// =======================================================================
// Kernel 3a: split-K proj partials. grid (SEQ/64, NSPLIT), tile 64x128.
//   g_Pp[z][s][e] = Z[s, z*256:(z+1)*256] @ proj[z*256:(z+1)*256, :]
// =======================================================================
__global__ __launch_bounds__(256, 2)
void gemm_proj_part(const float* __restrict__ proj)
{
    __shared__ float As[16 * 68];    // [k][r], padded
    __shared__ float Bs[16 * 128];

    const int tid  = threadIdx.x;
    const int row0 = blockIdx.x * 64;
    const int HK   = NH * EMB;            // 2048
    const int kb   = blockIdx.y * (HK / NSPLIT);  // 256-wide K chunk
    const int tx = tid & 15, ty = tid >> 4;

    u64 c2[4][4];
#pragma unroll
    for (int m = 0; m < 4; m++)
#pragma unroll
        for (int p = 0; p < 4; p++) c2[m][p] = 0ull;

#pragma unroll 1
    for (int k0 = 0; k0 < HK / NSPLIT; k0 += 16) {
        {
            int r = tid >> 2, c = (tid & 3) << 2;           // 64x16 -> 256 float4
            float4 v = *(const float4*)&g_Z[(row0 + r) * HK + kb + k0 + c];
            As[(c + 0) * 68 + r] = v.x;
            As[(c + 1) * 68 + r] = v.y;
            As[(c + 2) * 68 + r] = v.z;
            As[(c + 3) * 68 + r] = v.w;
        }
#pragma unroll
        for (int it = 0; it < 2; it++) {
            int idx = tid + it * 256;
            int rb = idx >> 5, cb = (idx & 31) << 2;        // 16x128 -> 512 float4
            *(float4*)&Bs[rb * 128 + cb] = *(const float4*)&proj[(kb + k0 + rb) * EMB + cb];
        }
        __syncthreads();
#pragma unroll
        for (int k = 0; k < 16; k++) {
            const ulonglong2* bpp = (const ulonglong2*)&Bs[k * 128 + tx * 8];
            ulonglong2 bA = bpp[0], bB = bpp[1];
            float4 a4 = *(const float4*)&As[k * 68 + ty * 4];
            const float* af = (const float*)&a4;
#pragma unroll
            for (int m = 0; m < 4; m++) {
                u64 a2 = dup2(af[m]);
                c2[m][0] = fma2(a2, bA.x, c2[m][0]);
                c2[m][1] = fma2(a2, bA.y, c2[m][1]);
                c2[m][2] = fma2(a2, bB.x, c2[m][2]);
                c2[m][3] = fma2(a2, bB.y, c2[m][3]);
            }
        }
        __syncthreads();
    }

#pragma unroll
    for (int m = 0; m < 4; m++) {
        float o[8];
#pragma unroll
        for (int p = 0; p < 4; p++) {
            float2 f = unpk(c2[m][p]);
            o[2 * p] = f.x; o[2 * p + 1] = f.y;
        }
        float* dst = &g_Pp[(blockIdx.y * SEQ + row0 + ty * 4 + m) * EMB + tx * 8];
        *(float4*)dst       = make_float4(o[0], o[1], o[2], o[3]);
        *(float4*)(dst + 4) = make_float4(o[4], o[5], o[6], o[7]);
    }
}

// Kernel 3b: deterministic reduction of NSPLIT partials into out.
__global__ __launch_bounds__(256)
void proj_reduce(float* __restrict__ out)
{
    int gid = blockIdx.x * 256 + threadIdx.x;       // 0..65535 float4 indices
    const float4* p = (const float4*)g_Pp;
    const int STR = SEQ * EMB / 4;                  // 65536
    float4 s = p[gid];
#pragma unroll
    for (int z = 1; z < NSPLIT; z++) {
        float4 t = p[z * STR + gid];
        s.x += t.x; s.y += t.y; s.z += t.z; s.w += t.w;
    }
    ((float4*)out)[gid] = s;
}

// =======================================================================
extern "C" void kernel_launch(void* const* d_in, const int* in_sizes, int n_in,
                              void* d_out, int out_size)
{
    (void)in_sizes; (void)n_in; (void)out_size;
    const float* x    = (const float*)d_in[0];
    const float* Wq   = (const float*)d_in[1];
    const float* bq   = (const float*)d_in[2];
    const float* Wk   = (const float*)d_in[3];
    const float* bk   = (const float*)d_in[4];
    const float* Wv   = (const float*)d_in[5];
    const float* bv   = (const float*)d_in[6];
    const float* proj = (const float*)d_in[7];
    float* out = (float*)d_out;

    static const int SMEM_ATTN = 160 * 1024;
    cudaFuncSetAttribute(attn_kernel, cudaFuncAttributeMaxDynamicSharedMemorySize, SMEM_ATTN);

    dim3 gq(SEQ / 128, 1, 48);
    gemm_qkv<<<gq, 256>>>(x, Wq, bq, Wk, bk, Wv, bv);

    dim3 ga(SEQ / 128, NH);
    attn_kernel<<<ga, 256, SMEM_ATTN>>>();

    dim3 gp(SEQ / 64, NSPLIT);
    gemm_proj_part<<<gp, 256>>>(proj);

    proj_reduce<<<SEQ * EMB / 1024, 256>>>(out);
}

// round 9
// speedup vs baseline: 3.2387x; 2.5502x over previous
#include <cuda_runtime.h>
#include <cuda_bf16.h>
#include <cstdint>

#define SEQ  2048
#define WORD 1024
#define EMB  128
#define NH   16
#define NSPLIT 8
#define QSC  0.1275174405080890f   /* (1/sqrt(128)) * log2(e) */

typedef unsigned long long u64;

// ---------------- device scratch (no allocations allowed) ----------------
__device__ float g_Z [SEQ * NH * EMB];        // [s][h*EMB + e]
__device__ float g_Pp[NSPLIT * SEQ * EMB];    // proj split-K partials

__device__ __align__(16) __nv_bfloat16 g_xhi[SEQ * WORD];
__device__ __align__(16) __nv_bfloat16 g_xlo[SEQ * WORD];
__device__ __align__(16) __nv_bfloat16 g_Whi[48 * WORD * EMB];   // [z][w][e]
__device__ __align__(16) __nv_bfloat16 g_Wlo[48 * WORD * EMB];
__device__ __align__(16) __nv_bfloat16 g_Qhi[NH * SEQ * EMB];    // scaled by QSC
__device__ __align__(16) __nv_bfloat16 g_Qlo[NH * SEQ * EMB];
__device__ __align__(16) __nv_bfloat16 g_Khi[NH * SEQ * EMB];
__device__ __align__(16) __nv_bfloat16 g_Klo[NH * SEQ * EMB];
__device__ __align__(16) __nv_bfloat16 g_Vhi[NH * SEQ * EMB];
__device__ __align__(16) __nv_bfloat16 g_Vlo[NH * SEQ * EMB];

// ---------------- f32x2 helpers (proj kernels) ----------------
__device__ __forceinline__ u64 dup2(float v) {
    u64 r; asm("mov.b64 %0, {%1, %1};" : "=l"(r) : "f"(v)); return r;
}
__device__ __forceinline__ u64 fma2(u64 a, u64 b, u64 c) {
    u64 d; asm("fma.rn.f32x2 %0, %1, %2, %3;" : "=l"(d) : "l"(a), "l"(b), "l"(c)); return d;
}
__device__ __forceinline__ float2 unpk(u64 v) {
    float2 f; asm("mov.b64 {%0, %1}, %2;" : "=f"(f.x), "=f"(f.y) : "l"(v)); return f;
}
__device__ __forceinline__ float ex2f_(float x) {
    float y; asm("ex2.approx.ftz.f32 %0, %1;" : "=f"(y) : "f"(x)); return y;
}

// ---------------- mma.sync / ldmatrix / cp.async helpers ----------------
__device__ __forceinline__ void mma16816(float* c, const uint32_t* a, uint32_t b0, uint32_t b1) {
    asm volatile(
        "mma.sync.aligned.m16n8k16.row.col.f32.bf16.bf16.f32 "
        "{%0,%1,%2,%3}, {%4,%5,%6,%7}, {%8,%9}, {%0,%1,%2,%3};"
        : "+f"(c[0]), "+f"(c[1]), "+f"(c[2]), "+f"(c[3])
        : "r"(a[0]), "r"(a[1]), "r"(a[2]), "r"(a[3]), "r"(b0), "r"(b1));
}
#define LDSM4(R, addr) \
    asm volatile("ldmatrix.sync.aligned.m8n8.x4.shared.b16 {%0,%1,%2,%3}, [%4];" \
        : "=r"((R)[0]), "=r"((R)[1]), "=r"((R)[2]), "=r"((R)[3]) : "r"(addr))
#define LDSM4T(R, addr) \
    asm volatile("ldmatrix.sync.aligned.m8n8.x4.trans.shared.b16 {%0,%1,%2,%3}, [%4];" \
        : "=r"((R)[0]), "=r"((R)[1]), "=r"((R)[2]), "=r"((R)[3]) : "r"(addr))

__device__ __forceinline__ void cpa(uint32_t dst, const void* src) {
    asm volatile("cp.async.cg.shared.global [%0], [%1], 16;" :: "r"(dst), "l"(src));
}
#define CP_COMMIT() asm volatile("cp.async.commit_group;")

__device__ __forceinline__ uint32_t smem_u32(const void* p) {
    uint32_t a;
    asm("{ .reg .u64 t; cvta.to.shared.u64 t, %1; cvt.u32.u64 %0, t; }" : "=r"(a) : "l"(p));
    return a;
}
__device__ __forceinline__ uint32_t pk(__nv_bfloat16 a, __nv_bfloat16 b) {
    uint16_t ua = *(uint16_t*)&a, ub = *(uint16_t*)&b;
    return (uint32_t)ua | ((uint32_t)ub << 16);
}
__device__ __forceinline__ void split_bf(float v, __nv_bfloat16& hi, __nv_bfloat16& lo) {
    hi = __float2bfloat16(v);
    lo = __float2bfloat16(v - __bfloat162float(hi));
}

// =======================================================================
// conv_x: split x into bf16 hi/lo. grid 2048 x 256, 4 elems/thread.
// =======================================================================
__global__ __launch_bounds__(256)
void conv_x(const float* __restrict__ x)
{
    int i = (blockIdx.x * 256 + threadIdx.x) * 4;
    float4 v = *(const float4*)&x[i];
    __nv_bfloat16 h0, h1, h2, h3, l0, l1, l2, l3;
    split_bf(v.x, h0, l0); split_bf(v.y, h1, l1);
    split_bf(v.z, h2, l2); split_bf(v.w, h3, l3);
    *(uint2*)&g_xhi[i] = make_uint2(pk(h0, h1), pk(h2, h3));
    *(uint2*)&g_xlo[i] = make_uint2(pk(l0, l1), pk(l2, l3));
}

// =======================================================================
// conv_w: split W (all 48 head-kinds) into bf16 hi/lo, layout unchanged.
// =======================================================================
__global__ __launch_bounds__(256)
void conv_w(const float* __restrict__ Wq, const float* __restrict__ Wk,
            const float* __restrict__ Wv)
{
    const int WE = WORD * EMB;
    int i = (blockIdx.x * 256 + threadIdx.x) * 4;
    int z = i / WE;
    int off = i - z * WE;
    const float* W = (z < 16 ? Wq : (z < 32 ? Wk : Wv));
    int hh = (z < 16 ? z : (z < 32 ? z - 16 : z - 32));
    float4 v = *(const float4*)&W[hh * WE + off];
    __nv_bfloat16 h0, h1, h2, h3, l0, l1, l2, l3;
    split_bf(v.x, h0, l0); split_bf(v.y, h1, l1);
    split_bf(v.z, h2, l2); split_bf(v.w, h3, l3);
    *(uint2*)&g_Whi[i] = make_uint2(pk(h0, h1), pk(h2, h3));
    *(uint2*)&g_Wlo[i] = make_uint2(pk(l0, l1), pk(l2, l3));
}

// =======================================================================
// gemm_qkv_mma: bf16 3-term split GEMM on HMMA.
//   grid (16 rowblocks, 48 z), 256 threads (8 warps, 16 rows each).
//   C[128 s][128 e] = x[128][1024] @ W[1024][128], chunks of K=64,
//   cp.async double-buffered. Epilogue: +bias, (Q: *QSC), split to bf16.
// =======================================================================
#define XT_SZ  18432                 /* 128 x 72 bf16 (144B rows) */
#define WT_SZ  17408                 /* 64 x 136 bf16 (272B rows) */
#define QKV_BUF (2*XT_SZ + 2*WT_SZ)  /* 71680 */
#define QKV_SMEM (2*QKV_BUF)         /* 143360 */

__global__ __launch_bounds__(256, 1)
void gemm_qkv_mma(const float* __restrict__ bq, const float* __restrict__ bk,
                  const float* __restrict__ bv)
{
    extern __shared__ char smem[];
    const uint32_t sb = smem_u32(smem);
    const int tid = threadIdx.x, w = tid >> 5, lane = tid & 31;
    const int z = blockIdx.y, kind = z >> 4, h = z & 15;
    const int row0 = blockIdx.x * 128;
    const float* bp = (kind == 0 ? bq : (kind == 1 ? bk : bv)) + h * EMB;

    const __nv_bfloat16* xh = g_xhi + (size_t)row0 * WORD;
    const __nv_bfloat16* xl = g_xlo + (size_t)row0 * WORD;
    const __nv_bfloat16* wh = g_Whi + (size_t)z * WORD * EMB;
    const __nv_bfloat16* wl = g_Wlo + (size_t)z * WORD * EMB;

    auto issue = [&](int kt) {
        uint32_t b = sb + (kt & 1) * QKV_BUF;
        int k0 = kt * 64;
#pragma unroll
        for (int t = 0; t < 4; t++) {                  // x tiles [128][64]
            int idx = tid + t * 256;
            int r = idx >> 3, s = idx & 7;
            uint32_t d = b + r * 144 + s * 16;
            cpa(d,         xh + r * WORD + k0 + s * 8);
            cpa(d + XT_SZ, xl + r * WORD + k0 + s * 8);
        }
#pragma unroll
        for (int t = 0; t < 4; t++) {                  // W tiles [64][128]
            int idx = tid + t * 256;
            int r = idx >> 4, s = idx & 15;
            uint32_t d = b + 2 * XT_SZ + r * 272 + s * 16;
            cpa(d,         wh + (k0 + r) * EMB + s * 8);
            cpa(d + WT_SZ, wl + (k0 + r) * EMB + s * 8);
        }
        CP_COMMIT();
    };

    issue(0); issue(1);

    float c[16][4];
#pragma unroll
    for (int j = 0; j < 16; j++)
#pragma unroll
        for (int p = 0; p < 4; p++) c[j][p] = 0.f;

    const int g = lane >> 2, t4 = lane & 3;
    // A (x, non-trans m16k16): row = w*16 + (lane&15), col byte = (lane>>4)*16
    const uint32_t a_off = (uint32_t)((w * 16 + (lane & 15)) * 144 + (lane >> 4) * 16);
    // B (W, trans k16n16): row = ((lane>>3)&1)*8 + (lane&7), col byte = (lane>>4)*16
    const uint32_t b_off = (uint32_t)(2 * XT_SZ +
        (((lane >> 3) & 1) * 8 + (lane & 7)) * 272 + (lane >> 4) * 16);

#pragma unroll 1
    for (int kt = 0; kt < 16; kt++) {
        if (kt < 15) asm volatile("cp.async.wait_group 1;");
        else         asm volatile("cp.async.wait_group 0;");
        __syncthreads();
        const uint32_t xb = sb + (kt & 1) * QKV_BUF;

#pragma unroll
        for (int kk = 0; kk < 4; kk++) {
            uint32_t ah[4], al[4];
            uint32_t aa = xb + a_off + kk * 32;
            LDSM4(ah, aa);
            LDSM4(al, aa + XT_SZ);
#pragma unroll
            for (int np = 0; np < 8; np++) {
                uint32_t ba = xb + b_off + kk * 16 * 272 + np * 32;
                uint32_t bh[4], bl[4];
                LDSM4T(bh, ba);
                LDSM4T(bl, ba + WT_SZ);
                mma16816(c[2 * np],     ah, bh[0], bh[1]);
                mma16816(c[2 * np],     al, bh[0], bh[1]);
                mma16816(c[2 * np],     ah, bl[0], bl[1]);
                mma16816(c[2 * np + 1], ah, bh[2], bh[3]);
                mma16816(c[2 * np + 1], al, bh[2], bh[3]);
                mma16816(c[2 * np + 1], ah, bl[2], bl[3]);
            }
        }
        __syncthreads();
        if (kt + 2 < 16) issue(kt + 2);
    }

    // ---- epilogue: bias, optional scale, split to bf16 hi/lo ----
    __nv_bfloat16 *dhi, *dlo;
    if (kind == 0)      { dhi = g_Qhi; dlo = g_Qlo; }
    else if (kind == 1) { dhi = g_Khi; dlo = g_Klo; }
    else                { dhi = g_Vhi; dlo = g_Vlo; }
    dhi += (size_t)h * SEQ * EMB;
    dlo += (size_t)h * SEQ * EMB;
    const float sc = (kind == 0) ? QSC : 1.0f;
    const int r0 = row0 + w * 16 + g, r1 = r0 + 8;

#pragma unroll
    for (int j = 0; j < 16; j++) {
        int col = 8 * j + 2 * t4;
        float b0 = __ldg(&bp[col]), b1 = __ldg(&bp[col + 1]);
        float v00 = (c[j][0] + b0) * sc, v01 = (c[j][1] + b1) * sc;
        float v10 = (c[j][2] + b0) * sc, v11 = (c[j][3] + b1) * sc;
        __nv_bfloat16 h00, h01, h10, h11, l00, l01, l10, l11;
        split_bf(v00, h00, l00); split_bf(v01, h01, l01);
        split_bf(v10, h10, l10); split_bf(v11, h11, l11);
        *(uint32_t*)&dhi[r0 * EMB + col] = pk(h00, h01);
        *(uint32_t*)&dlo[r0 * EMB + col] = pk(l00, l01);
        *(uint32_t*)&dhi[r1 * EMB + col] = pk(h10, h11);
        *(uint32_t*)&dlo[r1 * EMB + col] = pk(l10, l11);
    }
}

// =======================================================================
// attn_mma: FA2-style flash attention on HMMA, 3-term bf16 split.
//   grid (16, 16), 256 threads. BQ=128 (16 rows/warp), BK=64.
//   Smem: Qhi|Qlo [128][136] + 2 x (Khi|Klo|Vhi|Vlo [64][136]) = 204 KB.
// =======================================================================
#define QT_SZ  34816                  /* 128 x 136 bf16 */
#define KT_SZ  17408                  /* 64 x 136 bf16 */
#define AT_KV  (2*QT_SZ)              /* 69632 */
#define AT_BUF (4*KT_SZ)              /* 69632 */
#define ATT_SMEM (AT_KV + 2*AT_BUF)   /* 208896 */

__global__ __launch_bounds__(256, 1)
void attn_mma()
{
    extern __shared__ char smem[];
    const uint32_t sb = smem_u32(smem);
    const int tid = threadIdx.x, w = tid >> 5, lane = tid & 31;
    const int qb = blockIdx.x * 128, h = blockIdx.y;

    const __nv_bfloat16* Qh = g_Qhi + (size_t)h * SEQ * EMB + (size_t)qb * EMB;
    const __nv_bfloat16* Ql = g_Qlo + (size_t)h * SEQ * EMB + (size_t)qb * EMB;
    const __nv_bfloat16* Kh = g_Khi + (size_t)h * SEQ * EMB;
    const __nv_bfloat16* Kl = g_Klo + (size_t)h * SEQ * EMB;
    const __nv_bfloat16* Vh = g_Vhi + (size_t)h * SEQ * EMB;
    const __nv_bfloat16* Vl = g_Vlo + (size_t)h * SEQ * EMB;

    // Q tiles (group 0, together with K/V chunk 0)
#pragma unroll
    for (int t = 0; t < 8; t++) {
        int idx = tid + t * 256;
        int r = idx >> 4, s = idx & 15;
        uint32_t d = sb + r * 272 + s * 16;
        cpa(d,         Qh + r * EMB + s * 8);
        cpa(d + QT_SZ, Ql + r * EMB + s * 8);
    }
    auto issue = [&](int kt) {
        uint32_t b = sb + AT_KV + (kt & 1) * AT_BUF;
        int kb = kt * 64;
#pragma unroll
        for (int t = 0; t < 4; t++) {
            int idx = tid + t * 256;
            int r = idx >> 4, s = idx & 15;
            uint32_t d = b + r * 272 + s * 16;
            const int go = (kb + r) * EMB + s * 8;
            cpa(d,             Kh + go);
            cpa(d + KT_SZ,     Kl + go);
            cpa(d + 2 * KT_SZ, Vh + go);
            cpa(d + 3 * KT_SZ, Vl + go);
        }
        CP_COMMIT();
    };
    issue(0); issue(1);

    asm volatile("cp.async.wait_group 1;");
    __syncthreads();

    // preload Q fragments (constant over the whole kt loop)
    uint32_t qah[8][4], qal[8][4];
    const uint32_t qa_off = (uint32_t)((w * 16 + (lane & 15)) * 272 + (lane >> 4) * 16);
#pragma unroll
    for (int kk = 0; kk < 8; kk++) {
        uint32_t a = sb + qa_off + kk * 32;
        LDSM4(qah[kk], a);
        LDSM4(qal[kk], a + QT_SZ);
    }

    float o[16][4];
#pragma unroll
    for (int j = 0; j < 16; j++)
#pragma unroll
        for (int p = 0; p < 4; p++) o[j][p] = 0.f;
    float mrow0 = -1e30f, mrow1 = -1e30f, lrow0 = 0.f, lrow1 = 0.f;

    const int g = lane >> 2, t4 = lane & 3;
    // K (non-trans, n-major): row = nbase + ((lane>>4)<<3) + (lane&7); col byte += ((lane>>3)&1)*16
    const uint32_t kb_row = (uint32_t)(((lane >> 4) << 3) + (lane & 7));
    const uint32_t kb_cadd = (uint32_t)(((lane >> 3) & 1) * 16);
    // V (trans, k-major): row = kbase + ((lane>>3)&1)*8 + (lane&7); col byte += (lane>>4)*16
    const uint32_t vb_row = (uint32_t)((((lane >> 3) & 1) * 8) + (lane & 7));
    const uint32_t vb_cadd = (uint32_t)((lane >> 4) * 16);

#pragma unroll 1
    for (int kt = 0; kt < 32; kt++) {
        if (kt > 0) {
            if (kt < 31) asm volatile("cp.async.wait_group 1;");
            else         asm volatile("cp.async.wait_group 0;");
            __syncthreads();
        }
        const uint32_t kbuf = sb + AT_KV + (kt & 1) * AT_BUF;

        // ---- S = Q @ K^T (16x64 per warp), log2 domain ----
        float s[8][4];
#pragma unroll
        for (int j = 0; j < 8; j++)
#pragma unroll
            for (int p = 0; p < 4; p++) s[j][p] = 0.f;
#pragma unroll
        for (int kk = 0; kk < 8; kk++) {
#pragma unroll
            for (int np = 0; np < 4; np++) {
                uint32_t ba = kbuf + (np * 16 + kb_row) * 272 + kk * 32 + kb_cadd;
                uint32_t bh[4], bl[4];
                LDSM4(bh, ba);
                LDSM4(bl, ba + KT_SZ);
                mma16816(s[2 * np],     qah[kk], bh[0], bh[1]);
                mma16816(s[2 * np],     qal[kk], bh[0], bh[1]);
                mma16816(s[2 * np],     qah[kk], bl[0], bl[1]);
                mma16816(s[2 * np + 1], qah[kk], bh[2], bh[3]);
                mma16816(s[2 * np + 1], qal[kk], bh[2], bh[3]);
                mma16816(s[2 * np + 1], qah[kk], bl[2], bl[3]);
            }
        }

        // ---- online softmax (rows g, g+8; quad = 4 lanes sharing g) ----
        float mx0 = -1e30f, mx1 = -1e30f;
#pragma unroll
        for (int j = 0; j < 8; j++) {
            mx0 = fmaxf(mx0, fmaxf(s[j][0], s[j][1]));
            mx1 = fmaxf(mx1, fmaxf(s[j][2], s[j][3]));
        }
        mx0 = fmaxf(mx0, __shfl_xor_sync(0xffffffffu, mx0, 1));
        mx0 = fmaxf(mx0, __shfl_xor_sync(0xffffffffu, mx0, 2));
        mx1 = fmaxf(mx1, __shfl_xor_sync(0xffffffffu, mx1, 1));
        mx1 = fmaxf(mx1, __shfl_xor_sync(0xffffffffu, mx1, 2));
        float mn0 = fmaxf(mrow0, mx0), mn1 = fmaxf(mrow1, mx1);
        float al0 = ex2f_(mrow0 - mn0), al1 = ex2f_(mrow1 - mn1);
        float rs0 = 0.f, rs1 = 0.f;
#pragma unroll
        for (int j = 0; j < 8; j++) {
            s[j][0] = ex2f_(s[j][0] - mn0);
            s[j][1] = ex2f_(s[j][1] - mn0);
            s[j][2] = ex2f_(s[j][2] - mn1);
            s[j][3] = ex2f_(s[j][3] - mn1);
            rs0 += s[j][0] + s[j][1];
            rs1 += s[j][2] + s[j][3];
        }
        rs0 += __shfl_xor_sync(0xffffffffu, rs0, 1);
        rs0 += __shfl_xor_sync(0xffffffffu, rs0, 2);
        rs1 += __shfl_xor_sync(0xffffffffu, rs1, 1);
        rs1 += __shfl_xor_sync(0xffffffffu, rs1, 2);
        lrow0 = lrow0 * al0 + rs0; mrow0 = mn0;
        lrow1 = lrow1 * al1 + rs1; mrow1 = mn1;
#pragma unroll
        for (int j = 0; j < 16; j++) {
            o[j][0] *= al0; o[j][1] *= al0; o[j][2] *= al1; o[j][3] *= al1;
        }

        // ---- O += P @ V (P repacked C-frag -> A-frag, split hi/lo) ----
        const uint32_t vbuf = kbuf + 2 * KT_SZ;
#pragma unroll
        for (int kk = 0; kk < 4; kk++) {
            uint32_t pah[4], pal[4];
            {
                __nv_bfloat16 ph[8], pl[8];
                split_bf(s[2 * kk][0], ph[0], pl[0]);
                split_bf(s[2 * kk][1], ph[1], pl[1]);
                split_bf(s[2 * kk][2], ph[2], pl[2]);
                split_bf(s[2 * kk][3], ph[3], pl[3]);
                split_bf(s[2 * kk + 1][0], ph[4], pl[4]);
                split_bf(s[2 * kk + 1][1], ph[5], pl[5]);
                split_bf(s[2 * kk + 1][2], ph[6], pl[6]);
                split_bf(s[2 * kk + 1][3], ph[7], pl[7]);
                pah[0] = pk(ph[0], ph[1]); pah[1] = pk(ph[2], ph[3]);
                pah[2] = pk(ph[4], ph[5]); pah[3] = pk(ph[6], ph[7]);
                pal[0] = pk(pl[0], pl[1]); pal[1] = pk(pl[2], pl[3]);
                pal[2] = pk(pl[4], pl[5]); pal[3] = pk(pl[6], pl[7]);
            }
#pragma unroll
            for (int np = 0; np < 8; np++) {
                uint32_t va = vbuf + (kk * 16 + vb_row) * 272 + np * 32 + vb_cadd;
                uint32_t vh4[4], vl4[4];
                LDSM4T(vh4, va);
                LDSM4T(vl4, va + KT_SZ);
                mma16816(o[2 * np],     pah, vh4[0], vh4[1]);
                mma16816(o[2 * np],     pal, vh4[0], vh4[1]);
                mma16816(o[2 * np],     pah, vl4[0], vl4[1]);
                mma16816(o[2 * np + 1], pah, vh4[2], vh4[3]);
                mma16816(o[2 * np + 1], pal, vh4[2], vh4[3]);
                mma16816(o[2 * np + 1], pah, vl4[2], vl4[3]);
            }
        }
        __syncthreads();
        if (kt + 2 < 32) issue(kt + 2);
    }

    // ---- epilogue: normalize and write Z[s][h*EMB + e] ----
    const float rl0 = 1.0f / lrow0, rl1 = 1.0f / lrow1;
    const int r0 = qb + w * 16 + g, r1 = r0 + 8;
    float* Z0 = g_Z + (size_t)r0 * (NH * EMB) + h * EMB;
    float* Z1 = g_Z + (size_t)r1 * (NH * EMB) + h * EMB;
#pragma unroll
    for (int j = 0; j < 16; j++) {
        int col = 8 * j + 2 * t4;
        *(float2*)&Z0[col] = make_float2(o[j][0] * rl0, o[j][1] * rl0);
        *(float2*)&Z1[col] = make_float2(o[j][2] * rl1, o[j][3] * rl1);
    }
}

// =======================================================================
// Kernel 3a/3b: proj split-K + reduce (unchanged, passing since R7).
// =======================================================================
__global__ __launch_bounds__(256, 2)
void gemm_proj_part(const float* __restrict__ proj)
{
    __shared__ float As[16 * 68];
    __shared__ float Bs[16 * 128];

    const int tid  = threadIdx.x;
    const int row0 = blockIdx.x * 64;
    const int HK   = NH * EMB;
    const int kb   = blockIdx.y * (HK / NSPLIT);
    const int tx = tid & 15, ty = tid >> 4;

    u64 c2[4][4];
#pragma unroll
    for (int m = 0; m < 4; m++)
#pragma unroll
        for (int p = 0; p < 4; p++) c2[m][p] = 0ull;

#pragma unroll 1
    for (int k0 = 0; k0 < HK / NSPLIT; k0 += 16) {
        {
            int r = tid >> 2, c = (tid & 3) << 2;
            float4 v = *(const float4*)&g_Z[(row0 + r) * HK + kb + k0 + c];
            As[(c + 0) * 68 + r] = v.x;
            As[(c + 1) * 68 + r] = v.y;
            As[(c + 2) * 68 + r] = v.z;
            As[(c + 3) * 68 + r] = v.w;
        }
#pragma unroll
        for (int it = 0; it < 2; it++) {
            int idx = tid + it * 256;
            int rb = idx >> 5, cb = (idx & 31) << 2;
            *(float4*)&Bs[rb * 128 + cb] = *(const float4*)&proj[(kb + k0 + rb) * EMB + cb];
        }
        __syncthreads();
#pragma unroll
        for (int k = 0; k < 16; k++) {
            const ulonglong2* bpp = (const ulonglong2*)&Bs[k * 128 + tx * 8];
            ulonglong2 bA = bpp[0], bB = bpp[1];
            float4 a4 = *(const float4*)&As[k * 68 + ty * 4];
            const float* af = (const float*)&a4;
#pragma unroll
            for (int m = 0; m < 4; m++) {
                u64 a2 = dup2(af[m]);
                c2[m][0] = fma2(a2, bA.x, c2[m][0]);
                c2[m][1] = fma2(a2, bA.y, c2[m][1]);
                c2[m][2] = fma2(a2, bB.x, c2[m][2]);
                c2[m][3] = fma2(a2, bB.y, c2[m][3]);
            }
        }
        __syncthreads();
    }

#pragma unroll
    for (int m = 0; m < 4; m++) {
        float oo[8];
#pragma unroll
        for (int p = 0; p < 4; p++) {
            float2 f = unpk(c2[m][p]);
            oo[2 * p] = f.x; oo[2 * p + 1] = f.y;
        }
        float* dst = &g_Pp[(blockIdx.y * SEQ + row0 + ty * 4 + m) * EMB + tx * 8];
        *(float4*)dst       = make_float4(oo[0], oo[1], oo[2], oo[3]);
        *(float4*)(dst + 4) = make_float4(oo[4], oo[5], oo[6], oo[7]);
    }
}

__global__ __launch_bounds__(256)
void proj_reduce(float* __restrict__ out)
{
    int gid = blockIdx.x * 256 + threadIdx.x;
    const float4* p = (const float4*)g_Pp;
    const int STR = SEQ * EMB / 4;
    float4 s = p[gid];
#pragma unroll
    for (int z = 1; z < NSPLIT; z++) {
        float4 t = p[z * STR + gid];
        s.x += t.x; s.y += t.y; s.z += t.z; s.w += t.w;
    }
    ((float4*)out)[gid] = s;
}

// =======================================================================
extern "C" void kernel_launch(void* const* d_in, const int* in_sizes, int n_in,
                              void* d_out, int out_size)
{
    (void)in_sizes; (void)n_in; (void)out_size;
    const float* x    = (const float*)d_in[0];
    const float* Wq   = (const float*)d_in[1];
    const float* bq   = (const float*)d_in[2];
    const float* Wk   = (const float*)d_in[3];
    const float* bk   = (const float*)d_in[4];
    const float* Wv   = (const float*)d_in[5];
    const float* bv   = (const float*)d_in[6];
    const float* proj = (const float*)d_in[7];
    float* out = (float*)d_out;

    cudaFuncSetAttribute(gemm_qkv_mma, cudaFuncAttributeMaxDynamicSharedMemorySize, QKV_SMEM);
    cudaFuncSetAttribute(attn_mma,     cudaFuncAttributeMaxDynamicSharedMemorySize, ATT_SMEM);

    conv_x<<<SEQ * WORD / 1024, 256>>>(x);
    conv_w<<<48 * WORD * EMB / 1024, 256>>>(Wq, Wk, Wv);

    gemm_qkv_mma<<<dim3(SEQ / 128, 48), 256, QKV_SMEM>>>(bq, bk, bv);

    attn_mma<<<dim3(SEQ / 128, NH), 256, ATT_SMEM>>>();

    gemm_proj_part<<<dim3(SEQ / 64, NSPLIT), 256>>>(proj);
    proj_reduce<<<SEQ * EMB / 1024, 256>>>(out);
}

// round 10
// speedup vs baseline: 3.4271x; 1.0582x over previous
#include <cuda_runtime.h>
#include <cuda_bf16.h>
#include <cstdint>

#define SEQ  2048
#define WORD 1024
#define EMB  128
#define NH   16
#define NSPLIT 8
#define HK   (NH * EMB)            /* 2048 */
#define QSC  0.1275174405080890f   /* (1/sqrt(128)) * log2(e) */

typedef unsigned long long u64;

// ---------------- device scratch (no allocations allowed) ----------------
__device__ float g_Pp[NSPLIT * SEQ * EMB];    // proj split-K partials

__device__ __align__(16) __nv_bfloat16 g_xhi[SEQ * WORD];
__device__ __align__(16) __nv_bfloat16 g_xlo[SEQ * WORD];
__device__ __align__(16) __nv_bfloat16 g_Whi[48 * WORD * EMB];   // [z][w][e]
__device__ __align__(16) __nv_bfloat16 g_Wlo[48 * WORD * EMB];
__device__ __align__(16) __nv_bfloat16 g_Qhi[NH * SEQ * EMB];    // scaled by QSC
__device__ __align__(16) __nv_bfloat16 g_Qlo[NH * SEQ * EMB];
__device__ __align__(16) __nv_bfloat16 g_Khi[NH * SEQ * EMB];
__device__ __align__(16) __nv_bfloat16 g_Klo[NH * SEQ * EMB];
__device__ __align__(16) __nv_bfloat16 g_Vhi[NH * SEQ * EMB];
__device__ __align__(16) __nv_bfloat16 g_Vlo[NH * SEQ * EMB];
__device__ __align__(16) __nv_bfloat16 g_Zhi[SEQ * HK];          // [s][h*EMB+e]
__device__ __align__(16) __nv_bfloat16 g_Zlo[SEQ * HK];
__device__ __align__(16) __nv_bfloat16 g_Phi[HK * EMB];          // proj split
__device__ __align__(16) __nv_bfloat16 g_Plo[HK * EMB];

// ---------------- helpers ----------------
__device__ __forceinline__ float ex2f_(float x) {
    float y; asm("ex2.approx.ftz.f32 %0, %1;" : "=f"(y) : "f"(x)); return y;
}
__device__ __forceinline__ void mma16816(float* c, const uint32_t* a, uint32_t b0, uint32_t b1) {
    asm volatile(
        "mma.sync.aligned.m16n8k16.row.col.f32.bf16.bf16.f32 "
        "{%0,%1,%2,%3}, {%4,%5,%6,%7}, {%8,%9}, {%0,%1,%2,%3};"
        : "+f"(c[0]), "+f"(c[1]), "+f"(c[2]), "+f"(c[3])
        : "r"(a[0]), "r"(a[1]), "r"(a[2]), "r"(a[3]), "r"(b0), "r"(b1));
}
#define LDSM4(R, addr) \
    asm volatile("ldmatrix.sync.aligned.m8n8.x4.shared.b16 {%0,%1,%2,%3}, [%4];" \
        : "=r"((R)[0]), "=r"((R)[1]), "=r"((R)[2]), "=r"((R)[3]) : "r"(addr))
#define LDSM4T(R, addr) \
    asm volatile("ldmatrix.sync.aligned.m8n8.x4.trans.shared.b16 {%0,%1,%2,%3}, [%4];" \
        : "=r"((R)[0]), "=r"((R)[1]), "=r"((R)[2]), "=r"((R)[3]) : "r"(addr))
__device__ __forceinline__ void cpa(uint32_t dst, const void* src) {
    asm volatile("cp.async.cg.shared.global [%0], [%1], 16;" :: "r"(dst), "l"(src));
}
#define CP_COMMIT() asm volatile("cp.async.commit_group;")
__device__ __forceinline__ uint32_t smem_u32(const void* p) {
    uint32_t a;
    asm("{ .reg .u64 t; cvta.to.shared.u64 t, %1; cvt.u32.u64 %0, t; }" : "=r"(a) : "l"(p));
    return a;
}
__device__ __forceinline__ uint32_t pk(__nv_bfloat16 a, __nv_bfloat16 b) {
    uint16_t ua = *(uint16_t*)&a, ub = *(uint16_t*)&b;
    return (uint32_t)ua | ((uint32_t)ub << 16);
}
__device__ __forceinline__ void split_bf(float v, __nv_bfloat16& hi, __nv_bfloat16& lo) {
    hi = __float2bfloat16(v);
    lo = __float2bfloat16(v - __bfloat162float(hi));
}

// =======================================================================
// conv kernels: fp32 -> bf16 hi/lo splits
// =======================================================================
__global__ __launch_bounds__(256)
void conv_x(const float* __restrict__ x)
{
    int i = (blockIdx.x * 256 + threadIdx.x) * 4;
    float4 v = *(const float4*)&x[i];
    __nv_bfloat16 h0, h1, h2, h3, l0, l1, l2, l3;
    split_bf(v.x, h0, l0); split_bf(v.y, h1, l1);
    split_bf(v.z, h2, l2); split_bf(v.w, h3, l3);
    *(uint2*)&g_xhi[i] = make_uint2(pk(h0, h1), pk(h2, h3));
    *(uint2*)&g_xlo[i] = make_uint2(pk(l0, l1), pk(l2, l3));
}

__global__ __launch_bounds__(256)
void conv_w(const float* __restrict__ Wq, const float* __restrict__ Wk,
            const float* __restrict__ Wv)
{
    const int WE = WORD * EMB;
    int i = (blockIdx.x * 256 + threadIdx.x) * 4;
    int z = i / WE;
    int off = i - z * WE;
    const float* W = (z < 16 ? Wq : (z < 32 ? Wk : Wv));
    int hh = (z < 16 ? z : (z < 32 ? z - 16 : z - 32));
    float4 v = *(const float4*)&W[hh * WE + off];
    __nv_bfloat16 h0, h1, h2, h3, l0, l1, l2, l3;
    split_bf(v.x, h0, l0); split_bf(v.y, h1, l1);
    split_bf(v.z, h2, l2); split_bf(v.w, h3, l3);
    *(uint2*)&g_Whi[i] = make_uint2(pk(h0, h1), pk(h2, h3));
    *(uint2*)&g_Wlo[i] = make_uint2(pk(l0, l1), pk(l2, l3));
}

__global__ __launch_bounds__(256)
void conv_p(const float* __restrict__ proj)
{
    int i = (blockIdx.x * 256 + threadIdx.x) * 4;
    float4 v = *(const float4*)&proj[i];
    __nv_bfloat16 h0, h1, h2, h3, l0, l1, l2, l3;
    split_bf(v.x, h0, l0); split_bf(v.y, h1, l1);
    split_bf(v.z, h2, l2); split_bf(v.w, h3, l3);
    *(uint2*)&g_Phi[i] = make_uint2(pk(h0, h1), pk(h2, h3));
    *(uint2*)&g_Plo[i] = make_uint2(pk(l0, l1), pk(l2, l3));
}

// =======================================================================
// gemm_qkv_mma v2: 3-term bf16 split HMMA GEMM, 4x2 warp grid.
//   grid (16 rowblocks, 48 z), 256 threads.
//   Warp tile M=32, N=64 (halves per-mma ldsm traffic vs R9).
// =======================================================================
#define XT_SZ  18432                 /* 128 x 72 bf16 (144B rows) */
#define WT_SZ  17408                 /* 64 x 136 bf16 (272B rows) */
#define QKV_BUF (2*XT_SZ + 2*WT_SZ)  /* 71680 */
#define QKV_SMEM (2*QKV_BUF)         /* 143360 */

__global__ __launch_bounds__(256, 1)
void gemm_qkv_mma(const float* __restrict__ bq, const float* __restrict__ bk,
                  const float* __restrict__ bv)
{
    extern __shared__ char smem[];
    const uint32_t sb = smem_u32(smem);
    const int tid = threadIdx.x, w = tid >> 5, lane = tid & 31;
    const int z = blockIdx.y, kind = z >> 4, h = z & 15;
    const int row0 = blockIdx.x * 128;
    const float* bp = (kind == 0 ? bq : (kind == 1 ? bk : bv)) + h * EMB;
    const int wr = w >> 1, wc = w & 1;          // 4 row-groups x 2 col-groups

    const __nv_bfloat16* xh = g_xhi + (size_t)row0 * WORD;
    const __nv_bfloat16* xl = g_xlo + (size_t)row0 * WORD;
    const __nv_bfloat16* wh = g_Whi + (size_t)z * WORD * EMB;
    const __nv_bfloat16* wl = g_Wlo + (size_t)z * WORD * EMB;

    auto issue = [&](int kt) {
        uint32_t b = sb + (kt & 1) * QKV_BUF;
        int k0 = kt * 64;
#pragma unroll
        for (int t = 0; t < 4; t++) {                  // x tiles [128][64]
            int idx = tid + t * 256;
            int r = idx >> 3, s = idx & 7;
            uint32_t d = b + r * 144 + s * 16;
            cpa(d,         xh + r * WORD + k0 + s * 8);
            cpa(d + XT_SZ, xl + r * WORD + k0 + s * 8);
        }
#pragma unroll
        for (int t = 0; t < 4; t++) {                  // W tiles [64][128]
            int idx = tid + t * 256;
            int r = idx >> 4, s = idx & 15;
            uint32_t d = b + 2 * XT_SZ + r * 272 + s * 16;
            cpa(d,         wh + (k0 + r) * EMB + s * 8);
            cpa(d + WT_SZ, wl + (k0 + r) * EMB + s * 8);
        }
        CP_COMMIT();
    };
    issue(0); issue(1);

    float c[2][8][4];
#pragma unroll
    for (int rt = 0; rt < 2; rt++)
#pragma unroll
        for (int j = 0; j < 8; j++)
#pragma unroll
            for (int p = 0; p < 4; p++) c[rt][j][p] = 0.f;

    const int g = lane >> 2, t4 = lane & 3;
    // A rows: wr*32 + rt*16 + (lane&15); col byte = (lane>>4)*16 + kk*32
    const uint32_t a_off = (uint32_t)((wr * 32 + (lane & 15)) * 144 + (lane >> 4) * 16);
    // B rows: kk*16 + ((lane>>3)&1)*8 + (lane&7); col byte = wc*128 + np*32 + (lane>>4)*16
    const uint32_t b_off = (uint32_t)(2 * XT_SZ +
        (((lane >> 3) & 1) * 8 + (lane & 7)) * 272 + wc * 128 + (lane >> 4) * 16);

#pragma unroll 1
    for (int kt = 0; kt < 16; kt++) {
        if (kt < 15) asm volatile("cp.async.wait_group 1;");
        else         asm volatile("cp.async.wait_group 0;");
        __syncthreads();
        const uint32_t xb = sb + (kt & 1) * QKV_BUF;

#pragma unroll
        for (int kk = 0; kk < 4; kk++) {
            uint32_t ah[2][4], al[2][4];
#pragma unroll
            for (int rt = 0; rt < 2; rt++) {
                uint32_t aa = xb + a_off + rt * 16 * 144 + kk * 32;
                LDSM4(ah[rt], aa);
                LDSM4(al[rt], aa + XT_SZ);
            }
#pragma unroll
            for (int np = 0; np < 4; np++) {
                uint32_t ba = xb + b_off + kk * 16 * 272 + np * 32;
                uint32_t bh[4], bl[4];
                LDSM4T(bh, ba);
                LDSM4T(bl, ba + WT_SZ);
#pragma unroll
                for (int rt = 0; rt < 2; rt++) {
                    mma16816(c[rt][2 * np],     ah[rt], bh[0], bh[1]);
                    mma16816(c[rt][2 * np],     al[rt], bh[0], bh[1]);
                    mma16816(c[rt][2 * np],     ah[rt], bl[0], bl[1]);
                    mma16816(c[rt][2 * np + 1], ah[rt], bh[2], bh[3]);
                    mma16816(c[rt][2 * np + 1], al[rt], bh[2], bh[3]);
                    mma16816(c[rt][2 * np + 1], ah[rt], bl[2], bl[3]);
                }
            }
        }
        __syncthreads();
        if (kt + 2 < 16) issue(kt + 2);
    }

    // ---- epilogue: bias, optional scale, split to bf16 hi/lo ----
    __nv_bfloat16 *dhi, *dlo;
    if (kind == 0)      { dhi = g_Qhi; dlo = g_Qlo; }
    else if (kind == 1) { dhi = g_Khi; dlo = g_Klo; }
    else                { dhi = g_Vhi; dlo = g_Vlo; }
    dhi += (size_t)h * SEQ * EMB;
    dlo += (size_t)h * SEQ * EMB;
    const float sc = (kind == 0) ? QSC : 1.0f;

#pragma unroll
    for (int rt = 0; rt < 2; rt++) {
        const int r0 = row0 + wr * 32 + rt * 16 + g, r1 = r0 + 8;
#pragma unroll
        for (int j = 0; j < 8; j++) {
            int col = wc * 64 + 8 * j + 2 * t4;
            float b0 = __ldg(&bp[col]), b1 = __ldg(&bp[col + 1]);
            float v00 = (c[rt][j][0] + b0) * sc, v01 = (c[rt][j][1] + b1) * sc;
            float v10 = (c[rt][j][2] + b0) * sc, v11 = (c[rt][j][3] + b1) * sc;
            __nv_bfloat16 h00, h01, h10, h11, l00, l01, l10, l11;
            split_bf(v00, h00, l00); split_bf(v01, h01, l01);
            split_bf(v10, h10, l10); split_bf(v11, h11, l11);
            *(uint32_t*)&dhi[r0 * EMB + col] = pk(h00, h01);
            *(uint32_t*)&dlo[r0 * EMB + col] = pk(l00, l01);
            *(uint32_t*)&dhi[r1 * EMB + col] = pk(h10, h11);
            *(uint32_t*)&dlo[r1 * EMB + col] = pk(l10, l11);
        }
    }
}

// =======================================================================
// attn_mma: FA2-style flash attention on HMMA (mainloop unchanged from
// passing R9). Epilogue now emits Z as bf16 hi/lo for the mma proj.
// =======================================================================
#define QT_SZ  34816                  /* 128 x 136 bf16 */
#define KT_SZ  17408                  /* 64 x 136 bf16 */
#define AT_KV  (2*QT_SZ)              /* 69632 */
#define AT_BUF (4*KT_SZ)              /* 69632 */
#define ATT_SMEM (AT_KV + 2*AT_BUF)   /* 208896 */

__global__ __launch_bounds__(256, 1)
void attn_mma()
{
    extern __shared__ char smem[];
    const uint32_t sb = smem_u32(smem);
    const int tid = threadIdx.x, w = tid >> 5, lane = tid & 31;
    const int qb = blockIdx.x * 128, h = blockIdx.y;

    const __nv_bfloat16* Qh = g_Qhi + (size_t)h * SEQ * EMB + (size_t)qb * EMB;
    const __nv_bfloat16* Ql = g_Qlo + (size_t)h * SEQ * EMB + (size_t)qb * EMB;
    const __nv_bfloat16* Kh = g_Khi + (size_t)h * SEQ * EMB;
    const __nv_bfloat16* Kl = g_Klo + (size_t)h * SEQ * EMB;
    const __nv_bfloat16* Vh = g_Vhi + (size_t)h * SEQ * EMB;
    const __nv_bfloat16* Vl = g_Vlo + (size_t)h * SEQ * EMB;

#pragma unroll
    for (int t = 0; t < 8; t++) {
        int idx = tid + t * 256;
        int r = idx >> 4, s = idx & 15;
        uint32_t d = sb + r * 272 + s * 16;
        cpa(d,         Qh + r * EMB + s * 8);
        cpa(d + QT_SZ, Ql + r * EMB + s * 8);
    }
    auto issue = [&](int kt) {
        uint32_t b = sb + AT_KV + (kt & 1) * AT_BUF;
        int kb = kt * 64;
#pragma unroll
        for (int t = 0; t < 4; t++) {
            int idx = tid + t * 256;
            int r = idx >> 4, s = idx & 15;
            uint32_t d = b + r * 272 + s * 16;
            const int go = (kb + r) * EMB + s * 8;
            cpa(d,             Kh + go);
            cpa(d + KT_SZ,     Kl + go);
            cpa(d + 2 * KT_SZ, Vh + go);
            cpa(d + 3 * KT_SZ, Vl + go);
        }
        CP_COMMIT();
    };
    issue(0); issue(1);

    asm volatile("cp.async.wait_group 1;");
    __syncthreads();

    uint32_t qah[8][4], qal[8][4];
    const uint32_t qa_off = (uint32_t)((w * 16 + (lane & 15)) * 272 + (lane >> 4) * 16);
#pragma unroll
    for (int kk = 0; kk < 8; kk++) {
        uint32_t a = sb + qa_off + kk * 32;
        LDSM4(qah[kk], a);
        LDSM4(qal[kk], a + QT_SZ);
    }

    float o[16][4];
#pragma unroll
    for (int j = 0; j < 16; j++)
#pragma unroll
        for (int p = 0; p < 4; p++) o[j][p] = 0.f;
    float mrow0 = -1e30f, mrow1 = -1e30f, lrow0 = 0.f, lrow1 = 0.f;

    const int g = lane >> 2, t4 = lane & 3;
    const uint32_t kb_row = (uint32_t)(((lane >> 4) << 3) + (lane & 7));
    const uint32_t kb_cadd = (uint32_t)(((lane >> 3) & 1) * 16);
    const uint32_t vb_row = (uint32_t)((((lane >> 3) & 1) * 8) + (lane & 7));
    const uint32_t vb_cadd = (uint32_t)((lane >> 4) * 16);

#pragma unroll 1
    for (int kt = 0; kt < 32; kt++) {
        if (kt > 0) {
            if (kt < 31) asm volatile("cp.async.wait_group 1;");
            else         asm volatile("cp.async.wait_group 0;");
            __syncthreads();
        }
        const uint32_t kbuf = sb + AT_KV + (kt & 1) * AT_BUF;

        float s[8][4];
#pragma unroll
        for (int j = 0; j < 8; j++)
#pragma unroll
            for (int p = 0; p < 4; p++) s[j][p] = 0.f;
#pragma unroll
        for (int kk = 0; kk < 8; kk++) {
#pragma unroll
            for (int np = 0; np < 4; np++) {
                uint32_t ba = kbuf + (np * 16 + kb_row) * 272 + kk * 32 + kb_cadd;
                uint32_t bh[4], bl[4];
                LDSM4(bh, ba);
                LDSM4(bl, ba + KT_SZ);
                mma16816(s[2 * np],     qah[kk], bh[0], bh[1]);
                mma16816(s[2 * np],     qal[kk], bh[0], bh[1]);
                mma16816(s[2 * np],     qah[kk], bl[0], bl[1]);
                mma16816(s[2 * np + 1], qah[kk], bh[2], bh[3]);
                mma16816(s[2 * np + 1], qal[kk], bh[2], bh[3]);
                mma16816(s[2 * np + 1], qah[kk], bl[2], bl[3]);
            }
        }

        float mx0 = -1e30f, mx1 = -1e30f;
#pragma unroll
        for (int j = 0; j < 8; j++) {
            mx0 = fmaxf(mx0, fmaxf(s[j][0], s[j][1]));
            mx1 = fmaxf(mx1, fmaxf(s[j][2], s[j][3]));
        }
        mx0 = fmaxf(mx0, __shfl_xor_sync(0xffffffffu, mx0, 1));
        mx0 = fmaxf(mx0, __shfl_xor_sync(0xffffffffu, mx0, 2));
        mx1 = fmaxf(mx1, __shfl_xor_sync(0xffffffffu, mx1, 1));
        mx1 = fmaxf(mx1, __shfl_xor_sync(0xffffffffu, mx1, 2));
        float mn0 = fmaxf(mrow0, mx0), mn1 = fmaxf(mrow1, mx1);
        float al0 = ex2f_(mrow0 - mn0), al1 = ex2f_(mrow1 - mn1);
        float rs0 = 0.f, rs1 = 0.f;
#pragma unroll
        for (int j = 0; j < 8; j++) {
            s[j][0] = ex2f_(s[j][0] - mn0);
            s[j][1] = ex2f_(s[j][1] - mn0);
            s[j][2] = ex2f_(s[j][2] - mn1);
            s[j][3] = ex2f_(s[j][3] - mn1);
            rs0 += s[j][0] + s[j][1];
            rs1 += s[j][2] + s[j][3];
        }
        rs0 += __shfl_xor_sync(0xffffffffu, rs0, 1);
        rs0 += __shfl_xor_sync(0xffffffffu, rs0, 2);
        rs1 += __shfl_xor_sync(0xffffffffu, rs1, 1);
        rs1 += __shfl_xor_sync(0xffffffffu, rs1, 2);
        lrow0 = lrow0 * al0 + rs0; mrow0 = mn0;
        lrow1 = lrow1 * al1 + rs1; mrow1 = mn1;
#pragma unroll
        for (int j = 0; j < 16; j++) {
            o[j][0] *= al0; o[j][1] *= al0; o[j][2] *= al1; o[j][3] *= al1;
        }

        const uint32_t vbuf = kbuf + 2 * KT_SZ;
#pragma unroll
        for (int kk = 0; kk < 4; kk++) {
            uint32_t pah[4], pal[4];
            {
                __nv_bfloat16 ph[8], pl[8];
                split_bf(s[2 * kk][0], ph[0], pl[0]);
                split_bf(s[2 * kk][1], ph[1], pl[1]);
                split_bf(s[2 * kk][2], ph[2], pl[2]);
                split_bf(s[2 * kk][3], ph[3], pl[3]);
                split_bf(s[2 * kk + 1][0], ph[4], pl[4]);
                split_bf(s[2 * kk + 1][1], ph[5], pl[5]);
                split_bf(s[2 * kk + 1][2], ph[6], pl[6]);
                split_bf(s[2 * kk + 1][3], ph[7], pl[7]);
                pah[0] = pk(ph[0], ph[1]); pah[1] = pk(ph[2], ph[3]);
                pah[2] = pk(ph[4], ph[5]); pah[3] = pk(ph[6], ph[7]);
                pal[0] = pk(pl[0], pl[1]); pal[1] = pk(pl[2], pl[3]);
                pal[2] = pk(pl[4], pl[5]); pal[3] = pk(pl[6], pl[7]);
            }
#pragma unroll
            for (int np = 0; np < 8; np++) {
                uint32_t va = vbuf + (kk * 16 + vb_row) * 272 + np * 32 + vb_cadd;
                uint32_t vh4[4], vl4[4];
                LDSM4T(vh4, va);
                LDSM4T(vl4, va + KT_SZ);
                mma16816(o[2 * np],     pah, vh4[0], vh4[1]);
                mma16816(o[2 * np],     pal, vh4[0], vh4[1]);
                mma16816(o[2 * np],     pah, vl4[0], vl4[1]);
                mma16816(o[2 * np + 1], pah, vh4[2], vh4[3]);
                mma16816(o[2 * np + 1], pal, vh4[2], vh4[3]);
                mma16816(o[2 * np + 1], pah, vl4[2], vl4[3]);
            }
        }
        __syncthreads();
        if (kt + 2 < 32) issue(kt + 2);
    }

    // ---- epilogue: normalize, split to bf16 hi/lo into g_Zhi/g_Zlo ----
    const float rl0 = 1.0f / lrow0, rl1 = 1.0f / lrow1;
    const int r0 = qb + w * 16 + g, r1 = r0 + 8;
    __nv_bfloat16* Zh0 = g_Zhi + (size_t)r0 * HK + h * EMB;
    __nv_bfloat16* Zl0 = g_Zlo + (size_t)r0 * HK + h * EMB;
    __nv_bfloat16* Zh1 = g_Zhi + (size_t)r1 * HK + h * EMB;
    __nv_bfloat16* Zl1 = g_Zlo + (size_t)r1 * HK + h * EMB;
#pragma unroll
    for (int j = 0; j < 16; j++) {
        int col = 8 * j + 2 * t4;
        float v00 = o[j][0] * rl0, v01 = o[j][1] * rl0;
        float v10 = o[j][2] * rl1, v11 = o[j][3] * rl1;
        __nv_bfloat16 h00, h01, h10, h11, l00, l01, l10, l11;
        split_bf(v00, h00, l00); split_bf(v01, h01, l01);
        split_bf(v10, h10, l10); split_bf(v11, h11, l11);
        *(uint32_t*)&Zh0[col] = pk(h00, h01);
        *(uint32_t*)&Zl0[col] = pk(l00, l01);
        *(uint32_t*)&Zh1[col] = pk(h10, h11);
        *(uint32_t*)&Zl1[col] = pk(l10, l11);
    }
}

// =======================================================================
// gemm_proj_mma: split-K proj on HMMA, 3-term bf16 split.
//   grid (16 rowblocks, 8 ksplit), 256 threads, 4x2 warp grid.
//   Partial[128][128] = Zsplit[128][256] @ projsplit[256][128] -> g_Pp fp32.
// =======================================================================
__global__ __launch_bounds__(256, 1)
void gemm_proj_mma()
{
    extern __shared__ char smem[];
    const uint32_t sb = smem_u32(smem);
    const int tid = threadIdx.x, w = tid >> 5, lane = tid & 31;
    const int row0 = blockIdx.x * 128;
    const int ks   = blockIdx.y;                 // K chunk base = ks*256
    const int wr = w >> 1, wc = w & 1;

    const __nv_bfloat16* zh = g_Zhi + (size_t)row0 * HK + ks * 256;
    const __nv_bfloat16* zl = g_Zlo + (size_t)row0 * HK + ks * 256;
    const __nv_bfloat16* ph = g_Phi + (size_t)ks * 256 * EMB;
    const __nv_bfloat16* pl = g_Plo + (size_t)ks * 256 * EMB;

    auto issue = [&](int kt) {
        uint32_t b = sb + (kt & 1) * QKV_BUF;
        int k0 = kt * 64;
#pragma unroll
        for (int t = 0; t < 4; t++) {                  // Z tiles [128][64]
            int idx = tid + t * 256;
            int r = idx >> 3, s = idx & 7;
            uint32_t d = b + r * 144 + s * 16;
            cpa(d,         zh + r * HK + k0 + s * 8);
            cpa(d + XT_SZ, zl + r * HK + k0 + s * 8);
        }
#pragma unroll
        for (int t = 0; t < 4; t++) {                  // proj tiles [64][128]
            int idx = tid + t * 256;
            int r = idx >> 4, s = idx & 15;
            uint32_t d = b + 2 * XT_SZ + r * 272 + s * 16;
            cpa(d,         ph + (k0 + r) * EMB + s * 8);
            cpa(d + WT_SZ, pl + (k0 + r) * EMB + s * 8);
        }
        CP_COMMIT();
    };
    issue(0); issue(1);

    float c[2][8][4];
#pragma unroll
    for (int rt = 0; rt < 2; rt++)
#pragma unroll
        for (int j = 0; j < 8; j++)
#pragma unroll
            for (int p = 0; p < 4; p++) c[rt][j][p] = 0.f;

    const int g = lane >> 2, t4 = lane & 3;
    const uint32_t a_off = (uint32_t)((wr * 32 + (lane & 15)) * 144 + (lane >> 4) * 16);
    const uint32_t b_off = (uint32_t)(2 * XT_SZ +
        (((lane >> 3) & 1) * 8 + (lane & 7)) * 272 + wc * 128 + (lane >> 4) * 16);

#pragma unroll 1
    for (int kt = 0; kt < 4; kt++) {
        if (kt < 3) asm volatile("cp.async.wait_group 1;");
        else        asm volatile("cp.async.wait_group 0;");
        __syncthreads();
        const uint32_t xb = sb + (kt & 1) * QKV_BUF;

#pragma unroll
        for (int kk = 0; kk < 4; kk++) {
            uint32_t ah[2][4], al[2][4];
#pragma unroll
            for (int rt = 0; rt < 2; rt++) {
                uint32_t aa = xb + a_off + rt * 16 * 144 + kk * 32;
                LDSM4(ah[rt], aa);
                LDSM4(al[rt], aa + XT_SZ);
            }
#pragma unroll
            for (int np = 0; np < 4; np++) {
                uint32_t ba = xb + b_off + kk * 16 * 272 + np * 32;
                uint32_t bh[4], bl[4];
                LDSM4T(bh, ba);
                LDSM4T(bl, ba + WT_SZ);
#pragma unroll
                for (int rt = 0; rt < 2; rt++) {
                    mma16816(c[rt][2 * np],     ah[rt], bh[0], bh[1]);
                    mma16816(c[rt][2 * np],     al[rt], bh[0], bh[1]);
                    mma16816(c[rt][2 * np],     ah[rt], bl[0], bl[1]);
                    mma16816(c[rt][2 * np + 1], ah[rt], bh[2], bh[3]);
                    mma16816(c[rt][2 * np + 1], al[rt], bh[2], bh[3]);
                    mma16816(c[rt][2 * np + 1], ah[rt], bl[2], bl[3]);
                }
            }
        }
        __syncthreads();
        if (kt + 2 < 4) issue(kt + 2);
    }

    float* Pp = g_Pp + (size_t)blockIdx.y * SEQ * EMB;
#pragma unroll
    for (int rt = 0; rt < 2; rt++) {
        const int r0 = row0 + wr * 32 + rt * 16 + g, r1 = r0 + 8;
#pragma unroll
        for (int j = 0; j < 8; j++) {
            int col = wc * 64 + 8 * j + 2 * t4;
            *(float2*)&Pp[r0 * EMB + col] = make_float2(c[rt][j][0], c[rt][j][1]);
            *(float2*)&Pp[r1 * EMB + col] = make_float2(c[rt][j][2], c[rt][j][3]);
        }
    }
}

__global__ __launch_bounds__(256)
void proj_reduce(float* __restrict__ out)
{
    int gid = blockIdx.x * 256 + threadIdx.x;
    const float4* p = (const float4*)g_Pp;
    const int STR = SEQ * EMB / 4;
    float4 s = p[gid];
#pragma unroll
    for (int z = 1; z < NSPLIT; z++) {
        float4 t = p[z * STR + gid];
        s.x += t.x; s.y += t.y; s.z += t.z; s.w += t.w;
    }
    ((float4*)out)[gid] = s;
}

// =======================================================================
extern "C" void kernel_launch(void* const* d_in, const int* in_sizes, int n_in,
                              void* d_out, int out_size)
{
    (void)in_sizes; (void)n_in; (void)out_size;
    const float* x    = (const float*)d_in[0];
    const float* Wq   = (const float*)d_in[1];
    const float* bq   = (const float*)d_in[2];
    const float* Wk   = (const float*)d_in[3];
    const float* bk   = (const float*)d_in[4];
    const float* Wv   = (const float*)d_in[5];
    const float* bv   = (const float*)d_in[6];
    const float* proj = (const float*)d_in[7];
    float* out = (float*)d_out;

    cudaFuncSetAttribute(gemm_qkv_mma,  cudaFuncAttributeMaxDynamicSharedMemorySize, QKV_SMEM);
    cudaFuncSetAttribute(attn_mma,      cudaFuncAttributeMaxDynamicSharedMemorySize, ATT_SMEM);
    cudaFuncSetAttribute(gemm_proj_mma, cudaFuncAttributeMaxDynamicSharedMemorySize, QKV_SMEM);

    conv_x<<<SEQ * WORD / 1024, 256>>>(x);
    conv_w<<<48 * WORD * EMB / 1024, 256>>>(Wq, Wk, Wv);
    conv_p<<<HK * EMB / 1024, 256>>>(proj);

    gemm_qkv_mma<<<dim3(SEQ / 128, 48), 256, QKV_SMEM>>>(bq, bk, bv);

    attn_mma<<<dim3(SEQ / 128, NH), 256, ATT_SMEM>>>();

    gemm_proj_mma<<<dim3(SEQ / 128, NSPLIT), 256, QKV_SMEM>>>();
    proj_reduce<<<SEQ * EMB / 1024, 256>>>(out);
}

// round 11
// speedup vs baseline: 3.4519x; 1.0072x over previous
#include <cuda_runtime.h>
#include <cuda_bf16.h>
#include <cstdint>

#define SEQ  2048
#define WORD 1024
#define EMB  128
#define NH   16
#define NSPLIT 8
#define HK   (NH * EMB)            /* 2048 */
#define QSC  0.1275174405080890f   /* (1/sqrt(128)) * log2(e) */

typedef unsigned long long u64;

// ---------------- device scratch (no allocations allowed) ----------------
__device__ float g_Pp[NSPLIT * SEQ * EMB];    // proj split-K partials

__device__ __align__(16) __nv_bfloat16 g_xhi[SEQ * WORD];
__device__ __align__(16) __nv_bfloat16 g_xlo[SEQ * WORD];
__device__ __align__(16) __nv_bfloat16 g_Whi[48 * WORD * EMB];   // [z][w][e]
__device__ __align__(16) __nv_bfloat16 g_Wlo[48 * WORD * EMB];
__device__ __align__(16) __nv_bfloat16 g_Qhi[NH * SEQ * EMB];    // scaled by QSC
__device__ __align__(16) __nv_bfloat16 g_Qlo[NH * SEQ * EMB];
__device__ __align__(16) __nv_bfloat16 g_Khi[NH * SEQ * EMB];
__device__ __align__(16) __nv_bfloat16 g_Klo[NH * SEQ * EMB];
__device__ __align__(16) __nv_bfloat16 g_Vhi[NH * SEQ * EMB];
__device__ __align__(16) __nv_bfloat16 g_Vlo[NH * SEQ * EMB];
__device__ __align__(16) __nv_bfloat16 g_Zhi[SEQ * HK];          // [s][h*EMB+e]
__device__ __align__(16) __nv_bfloat16 g_Zlo[SEQ * HK];
__device__ __align__(16) __nv_bfloat16 g_Phi[HK * EMB];          // proj split
__device__ __align__(16) __nv_bfloat16 g_Plo[HK * EMB];

// ---------------- helpers ----------------
__device__ __forceinline__ float ex2f_(float x) {
    float y; asm("ex2.approx.ftz.f32 %0, %1;" : "=f"(y) : "f"(x)); return y;
}
__device__ __forceinline__ void mma16816(float* c, const uint32_t* a, uint32_t b0, uint32_t b1) {
    asm volatile(
        "mma.sync.aligned.m16n8k16.row.col.f32.bf16.bf16.f32 "
        "{%0,%1,%2,%3}, {%4,%5,%6,%7}, {%8,%9}, {%0,%1,%2,%3};"
        : "+f"(c[0]), "+f"(c[1]), "+f"(c[2]), "+f"(c[3])
        : "r"(a[0]), "r"(a[1]), "r"(a[2]), "r"(a[3]), "r"(b0), "r"(b1));
}
#define LDSM4(R, addr) \
    asm volatile("ldmatrix.sync.aligned.m8n8.x4.shared.b16 {%0,%1,%2,%3}, [%4];" \
        : "=r"((R)[0]), "=r"((R)[1]), "=r"((R)[2]), "=r"((R)[3]) : "r"(addr))
#define LDSM4T(R, addr) \
    asm volatile("ldmatrix.sync.aligned.m8n8.x4.trans.shared.b16 {%0,%1,%2,%3}, [%4];" \
        : "=r"((R)[0]), "=r"((R)[1]), "=r"((R)[2]), "=r"((R)[3]) : "r"(addr))
__device__ __forceinline__ void cpa(uint32_t dst, const void* src) {
    asm volatile("cp.async.cg.shared.global [%0], [%1], 16;" :: "r"(dst), "l"(src));
}
#define CP_COMMIT() asm volatile("cp.async.commit_group;")
__device__ __forceinline__ uint32_t smem_u32(const void* p) {
    uint32_t a;
    asm("{ .reg .u64 t; cvta.to.shared.u64 t, %1; cvt.u32.u64 %0, t; }" : "=r"(a) : "l"(p));
    return a;
}
__device__ __forceinline__ uint32_t pk(__nv_bfloat16 a, __nv_bfloat16 b) {
    uint16_t ua = *(uint16_t*)&a, ub = *(uint16_t*)&b;
    return (uint32_t)ua | ((uint32_t)ub << 16);
}
__device__ __forceinline__ void split_bf(float v, __nv_bfloat16& hi, __nv_bfloat16& lo) {
    hi = __float2bfloat16(v);
    lo = __float2bfloat16(v - __bfloat162float(hi));
}

// =======================================================================
// conv kernels: fp32 -> bf16 hi/lo splits
// =======================================================================
__global__ __launch_bounds__(256)
void conv_x(const float* __restrict__ x)
{
    int i = (blockIdx.x * 256 + threadIdx.x) * 4;
    float4 v = *(const float4*)&x[i];
    __nv_bfloat16 h0, h1, h2, h3, l0, l1, l2, l3;
    split_bf(v.x, h0, l0); split_bf(v.y, h1, l1);
    split_bf(v.z, h2, l2); split_bf(v.w, h3, l3);
    *(uint2*)&g_xhi[i] = make_uint2(pk(h0, h1), pk(h2, h3));
    *(uint2*)&g_xlo[i] = make_uint2(pk(l0, l1), pk(l2, l3));
}

__global__ __launch_bounds__(256)
void conv_w(const float* __restrict__ Wq, const float* __restrict__ Wk,
            const float* __restrict__ Wv)
{
    const int WE = WORD * EMB;
    int i = (blockIdx.x * 256 + threadIdx.x) * 4;
    int z = i / WE;
    int off = i - z * WE;
    const float* W = (z < 16 ? Wq : (z < 32 ? Wk : Wv));
    int hh = (z < 16 ? z : (z < 32 ? z - 16 : z - 32));
    float4 v = *(const float4*)&W[hh * WE + off];
    __nv_bfloat16 h0, h1, h2, h3, l0, l1, l2, l3;
    split_bf(v.x, h0, l0); split_bf(v.y, h1, l1);
    split_bf(v.z, h2, l2); split_bf(v.w, h3, l3);
    *(uint2*)&g_Whi[i] = make_uint2(pk(h0, h1), pk(h2, h3));
    *(uint2*)&g_Wlo[i] = make_uint2(pk(l0, l1), pk(l2, l3));
}

__global__ __launch_bounds__(256)
void conv_p(const float* __restrict__ proj)
{
    int i = (blockIdx.x * 256 + threadIdx.x) * 4;
    float4 v = *(const float4*)&proj[i];
    __nv_bfloat16 h0, h1, h2, h3, l0, l1, l2, l3;
    split_bf(v.x, h0, l0); split_bf(v.y, h1, l1);
    split_bf(v.z, h2, l2); split_bf(v.w, h3, l3);
    *(uint2*)&g_Phi[i] = make_uint2(pk(h0, h1), pk(h2, h3));
    *(uint2*)&g_Plo[i] = make_uint2(pk(l0, l1), pk(l2, l3));
}

// =======================================================================
// gemm_qkv_mma v3: 3-term bf16 split HMMA GEMM, 4x2 warp grid,
//   3-stage cp.async ring -> ONE __syncthreads per chunk.
// =======================================================================
#define XT_SZ  18432                 /* 128 x 72 bf16 (144B rows) */
#define WT_SZ  17408                 /* 64 x 136 bf16 (272B rows) */
#define QKV_BUF (2*XT_SZ + 2*WT_SZ)  /* 71680 */
#define QKV_SMEM3 (3*QKV_BUF)        /* 215040 */
#define PRJ_SMEM  (2*QKV_BUF)        /* 143360 (proj keeps 2-stage) */

__global__ __launch_bounds__(256, 1)
void gemm_qkv_mma(const float* __restrict__ bq, const float* __restrict__ bk,
                  const float* __restrict__ bv)
{
    extern __shared__ char smem[];
    const uint32_t sb = smem_u32(smem);
    const int tid = threadIdx.x, w = tid >> 5, lane = tid & 31;
    const int z = blockIdx.y, kind = z >> 4, h = z & 15;
    const int row0 = blockIdx.x * 128;
    const float* bp = (kind == 0 ? bq : (kind == 1 ? bk : bv)) + h * EMB;
    const int wr = w >> 1, wc = w & 1;          // 4 row-groups x 2 col-groups

    const __nv_bfloat16* xh = g_xhi + (size_t)row0 * WORD;
    const __nv_bfloat16* xl = g_xlo + (size_t)row0 * WORD;
    const __nv_bfloat16* wh = g_Whi + (size_t)z * WORD * EMB;
    const __nv_bfloat16* wl = g_Wlo + (size_t)z * WORD * EMB;

    auto issue = [&](int kt) {
        uint32_t b = sb + (kt % 3) * QKV_BUF;
        int k0 = kt * 64;
#pragma unroll
        for (int t = 0; t < 4; t++) {                  // x tiles [128][64]
            int idx = tid + t * 256;
            int r = idx >> 3, s = idx & 7;
            uint32_t d = b + r * 144 + s * 16;
            cpa(d,         xh + r * WORD + k0 + s * 8);
            cpa(d + XT_SZ, xl + r * WORD + k0 + s * 8);
        }
#pragma unroll
        for (int t = 0; t < 4; t++) {                  // W tiles [64][128]
            int idx = tid + t * 256;
            int r = idx >> 4, s = idx & 15;
            uint32_t d = b + 2 * XT_SZ + r * 272 + s * 16;
            cpa(d,         wh + (k0 + r) * EMB + s * 8);
            cpa(d + WT_SZ, wl + (k0 + r) * EMB + s * 8);
        }
        CP_COMMIT();
    };
    issue(0); issue(1);

    float c[2][8][4];
#pragma unroll
    for (int rt = 0; rt < 2; rt++)
#pragma unroll
        for (int j = 0; j < 8; j++)
#pragma unroll
            for (int p = 0; p < 4; p++) c[rt][j][p] = 0.f;

    const int g = lane >> 2, t4 = lane & 3;
    const uint32_t a_off = (uint32_t)((wr * 32 + (lane & 15)) * 144 + (lane >> 4) * 16);
    const uint32_t b_off = (uint32_t)(2 * XT_SZ +
        (((lane >> 3) & 1) * 8 + (lane & 7)) * 272 + wc * 128 + (lane >> 4) * 16);

#pragma unroll 1
    for (int kt = 0; kt < 16; kt++) {
        asm volatile("cp.async.wait_group 1;");   // chunk kt arrived
        __syncthreads();                           // visible to all; buf (kt+2)%3 free
        if (kt + 2 < 16) issue(kt + 2);
        const uint32_t xb = sb + (kt % 3) * QKV_BUF;

#pragma unroll
        for (int kk = 0; kk < 4; kk++) {
            uint32_t ah[2][4], al[2][4];
#pragma unroll
            for (int rt = 0; rt < 2; rt++) {
                uint32_t aa = xb + a_off + rt * 16 * 144 + kk * 32;
                LDSM4(ah[rt], aa);
                LDSM4(al[rt], aa + XT_SZ);
            }
#pragma unroll
            for (int np = 0; np < 4; np++) {
                uint32_t ba = xb + b_off + kk * 16 * 272 + np * 32;
                uint32_t bh[4], bl[4];
                LDSM4T(bh, ba);
                LDSM4T(bl, ba + WT_SZ);
#pragma unroll
                for (int rt = 0; rt < 2; rt++) {
                    mma16816(c[rt][2 * np],     ah[rt], bh[0], bh[1]);
                    mma16816(c[rt][2 * np],     al[rt], bh[0], bh[1]);
                    mma16816(c[rt][2 * np],     ah[rt], bl[0], bl[1]);
                    mma16816(c[rt][2 * np + 1], ah[rt], bh[2], bh[3]);
                    mma16816(c[rt][2 * np + 1], al[rt], bh[2], bh[3]);
                    mma16816(c[rt][2 * np + 1], ah[rt], bl[2], bl[3]);
                }
            }
        }
    }

    // ---- epilogue: bias, optional scale, split to bf16 hi/lo ----
    __nv_bfloat16 *dhi, *dlo;
    if (kind == 0)      { dhi = g_Qhi; dlo = g_Qlo; }
    else if (kind == 1) { dhi = g_Khi; dlo = g_Klo; }
    else                { dhi = g_Vhi; dlo = g_Vlo; }
    dhi += (size_t)h * SEQ * EMB;
    dlo += (size_t)h * SEQ * EMB;
    const float sc = (kind == 0) ? QSC : 1.0f;

#pragma unroll
    for (int rt = 0; rt < 2; rt++) {
        const int r0 = row0 + wr * 32 + rt * 16 + g, r1 = r0 + 8;
#pragma unroll
        for (int j = 0; j < 8; j++) {
            int col = wc * 64 + 8 * j + 2 * t4;
            float b0 = __ldg(&bp[col]), b1 = __ldg(&bp[col + 1]);
            float v00 = (c[rt][j][0] + b0) * sc, v01 = (c[rt][j][1] + b1) * sc;
            float v10 = (c[rt][j][2] + b0) * sc, v11 = (c[rt][j][3] + b1) * sc;
            __nv_bfloat16 h00, h01, h10, h11, l00, l01, l10, l11;
            split_bf(v00, h00, l00); split_bf(v01, h01, l01);
            split_bf(v10, h10, l10); split_bf(v11, h11, l11);
            *(uint32_t*)&dhi[r0 * EMB + col] = pk(h00, h01);
            *(uint32_t*)&dlo[r0 * EMB + col] = pk(l00, l01);
            *(uint32_t*)&dhi[r1 * EMB + col] = pk(h10, h11);
            *(uint32_t*)&dlo[r1 * EMB + col] = pk(l10, l11);
        }
    }
}

// =======================================================================
// attn_mma v2: FA2 flash attention on HMMA, 3-stage KV ring.
//   Q's smem region doubles as ring buffer 2 (Q fragments are extracted
//   to registers before chunk 2 overwrites it). ONE barrier per chunk.
// =======================================================================
#define QT_SZ  34816                  /* 128 x 136 bf16 */
#define KT_SZ  17408                  /* 64 x 136 bf16 */
#define AT_BUF (4*KT_SZ)              /* 69632 = 2*QT_SZ */
#define ATT_SMEM (3*AT_BUF)           /* 208896 */

__global__ __launch_bounds__(256, 1)
void attn_mma()
{
    extern __shared__ char smem[];
    const uint32_t sb = smem_u32(smem);
    const int tid = threadIdx.x, w = tid >> 5, lane = tid & 31;
    const int qb = blockIdx.x * 128, h = blockIdx.y;

    const __nv_bfloat16* Qh = g_Qhi + (size_t)h * SEQ * EMB + (size_t)qb * EMB;
    const __nv_bfloat16* Ql = g_Qlo + (size_t)h * SEQ * EMB + (size_t)qb * EMB;
    const __nv_bfloat16* Kh = g_Khi + (size_t)h * SEQ * EMB;
    const __nv_bfloat16* Kl = g_Klo + (size_t)h * SEQ * EMB;
    const __nv_bfloat16* Vh = g_Vhi + (size_t)h * SEQ * EMB;
    const __nv_bfloat16* Vl = g_Vlo + (size_t)h * SEQ * EMB;

    // Q -> ring buffer 2 region (temporarily)
    const uint32_t qbase = sb + 2 * AT_BUF;
#pragma unroll
    for (int t = 0; t < 8; t++) {
        int idx = tid + t * 256;
        int r = idx >> 4, s = idx & 15;
        uint32_t d = qbase + r * 272 + s * 16;
        cpa(d,         Qh + r * EMB + s * 8);
        cpa(d + QT_SZ, Ql + r * EMB + s * 8);
    }
    CP_COMMIT();

    auto issue = [&](int kt) {
        uint32_t b = sb + (kt % 3) * AT_BUF;
        int kb = kt * 64;
#pragma unroll
        for (int t = 0; t < 4; t++) {
            int idx = tid + t * 256;
            int r = idx >> 4, s = idx & 15;
            uint32_t d = b + r * 272 + s * 16;
            const int go = (kb + r) * EMB + s * 8;
            cpa(d,             Kh + go);
            cpa(d + KT_SZ,     Kl + go);
            cpa(d + 2 * KT_SZ, Vh + go);
            cpa(d + 3 * KT_SZ, Vl + go);
        }
        CP_COMMIT();
    };
    issue(0); issue(1);

    asm volatile("cp.async.wait_group 2;");   // Q arrived
    __syncthreads();

    // extract Q fragments (registers, persistent)
    uint32_t qah[8][4], qal[8][4];
    const uint32_t qa_off = (uint32_t)((w * 16 + (lane & 15)) * 272 + (lane >> 4) * 16);
#pragma unroll
    for (int kk = 0; kk < 8; kk++) {
        uint32_t a = qbase + qa_off + kk * 32;
        LDSM4(qah[kk], a);
        LDSM4(qal[kk], a + QT_SZ);
    }
    __syncthreads();                           // Q region now dead -> buffer 2

    float o[16][4];
#pragma unroll
    for (int j = 0; j < 16; j++)
#pragma unroll
        for (int p = 0; p < 4; p++) o[j][p] = 0.f;
    float mrow0 = -1e30f, mrow1 = -1e30f, lrow0 = 0.f, lrow1 = 0.f;

    const int g = lane >> 2, t4 = lane & 3;
    const uint32_t kb_row = (uint32_t)(((lane >> 4) << 3) + (lane & 7));
    const uint32_t kb_cadd = (uint32_t)(((lane >> 3) & 1) * 16);
    const uint32_t vb_row = (uint32_t)((((lane >> 3) & 1) * 8) + (lane & 7));
    const uint32_t vb_cadd = (uint32_t)((lane >> 4) * 16);

#pragma unroll 1
    for (int kt = 0; kt < 32; kt++) {
        asm volatile("cp.async.wait_group 1;");   // chunk kt arrived
        __syncthreads();
        if (kt + 2 < 32) issue(kt + 2);
        const uint32_t kbuf = sb + (kt % 3) * AT_BUF;

        float s[8][4];
#pragma unroll
        for (int j = 0; j < 8; j++)
#pragma unroll
            for (int p = 0; p < 4; p++) s[j][p] = 0.f;
#pragma unroll
        for (int kk = 0; kk < 8; kk++) {
#pragma unroll
            for (int np = 0; np < 4; np++) {
                uint32_t ba = kbuf + (np * 16 + kb_row) * 272 + kk * 32 + kb_cadd;
                uint32_t bh[4], bl[4];
                LDSM4(bh, ba);
                LDSM4(bl, ba + KT_SZ);
                mma16816(s[2 * np],     qah[kk], bh[0], bh[1]);
                mma16816(s[2 * np],     qal[kk], bh[0], bh[1]);
                mma16816(s[2 * np],     qah[kk], bl[0], bl[1]);
                mma16816(s[2 * np + 1], qah[kk], bh[2], bh[3]);
                mma16816(s[2 * np + 1], qal[kk], bh[2], bh[3]);
                mma16816(s[2 * np + 1], qah[kk], bl[2], bl[3]);
            }
        }

        float mx0 = -1e30f, mx1 = -1e30f;
#pragma unroll
        for (int j = 0; j < 8; j++) {
            mx0 = fmaxf(mx0, fmaxf(s[j][0], s[j][1]));
            mx1 = fmaxf(mx1, fmaxf(s[j][2], s[j][3]));
        }
        mx0 = fmaxf(mx0, __shfl_xor_sync(0xffffffffu, mx0, 1));
        mx0 = fmaxf(mx0, __shfl_xor_sync(0xffffffffu, mx0, 2));
        mx1 = fmaxf(mx1, __shfl_xor_sync(0xffffffffu, mx1, 1));
        mx1 = fmaxf(mx1, __shfl_xor_sync(0xffffffffu, mx1, 2));
        float mn0 = fmaxf(mrow0, mx0), mn1 = fmaxf(mrow1, mx1);
        float al0 = ex2f_(mrow0 - mn0), al1 = ex2f_(mrow1 - mn1);
        float rs0 = 0.f, rs1 = 0.f;
#pragma unroll
        for (int j = 0; j < 8; j++) {
            s[j][0] = ex2f_(s[j][0] - mn0);
            s[j][1] = ex2f_(s[j][1] - mn0);
            s[j][2] = ex2f_(s[j][2] - mn1);
            s[j][3] = ex2f_(s[j][3] - mn1);
            rs0 += s[j][0] + s[j][1];
            rs1 += s[j][2] + s[j][3];
        }
        rs0 += __shfl_xor_sync(0xffffffffu, rs0, 1);
        rs0 += __shfl_xor_sync(0xffffffffu, rs0, 2);
        rs1 += __shfl_xor_sync(0xffffffffu, rs1, 1);
        rs1 += __shfl_xor_sync(0xffffffffu, rs1, 2);
        lrow0 = lrow0 * al0 + rs0; mrow0 = mn0;
        lrow1 = lrow1 * al1 + rs1; mrow1 = mn1;
#pragma unroll
        for (int j = 0; j < 16; j++) {
            o[j][0] *= al0; o[j][1] *= al0; o[j][2] *= al1; o[j][3] *= al1;
        }

        const uint32_t vbuf = kbuf + 2 * KT_SZ;
#pragma unroll
        for (int kk = 0; kk < 4; kk++) {
            uint32_t pah[4], pal[4];
            {
                __nv_bfloat16 ph[8], pl[8];
                split_bf(s[2 * kk][0], ph[0], pl[0]);
                split_bf(s[2 * kk][1], ph[1], pl[1]);
                split_bf(s[2 * kk][2], ph[2], pl[2]);
                split_bf(s[2 * kk][3], ph[3], pl[3]);
                split_bf(s[2 * kk + 1][0], ph[4], pl[4]);
                split_bf(s[2 * kk + 1][1], ph[5], pl[5]);
                split_bf(s[2 * kk + 1][2], ph[6], pl[6]);
                split_bf(s[2 * kk + 1][3], ph[7], pl[7]);
                pah[0] = pk(ph[0], ph[1]); pah[1] = pk(ph[2], ph[3]);
                pah[2] = pk(ph[4], ph[5]); pah[3] = pk(ph[6], ph[7]);
                pal[0] = pk(pl[0], pl[1]); pal[1] = pk(pl[2], pl[3]);
                pal[2] = pk(pl[4], pl[5]); pal[3] = pk(pl[6], pl[7]);
            }
#pragma unroll
            for (int np = 0; np < 8; np++) {
                uint32_t va = vbuf + (kk * 16 + vb_row) * 272 + np * 32 + vb_cadd;
                uint32_t vh4[4], vl4[4];
                LDSM4T(vh4, va);
                LDSM4T(vl4, va + KT_SZ);
                mma16816(o[2 * np],     pah, vh4[0], vh4[1]);
                mma16816(o[2 * np],     pal, vh4[0], vh4[1]);
                mma16816(o[2 * np],     pah, vl4[0], vl4[1]);
                mma16816(o[2 * np + 1], pah, vh4[2], vh4[3]);
                mma16816(o[2 * np + 1], pal, vh4[2], vh4[3]);
                mma16816(o[2 * np + 1], pah, vl4[2], vl4[3]);
            }
        }
    }

    // ---- epilogue: normalize, split to bf16 hi/lo into g_Zhi/g_Zlo ----
    const float rl0 = 1.0f / lrow0, rl1 = 1.0f / lrow1;
    const int r0 = qb + w * 16 + g, r1 = r0 + 8;
    __nv_bfloat16* Zh0 = g_Zhi + (size_t)r0 * HK + h * EMB;
    __nv_bfloat16* Zl0 = g_Zlo + (size_t)r0 * HK + h * EMB;
    __nv_bfloat16* Zh1 = g_Zhi + (size_t)r1 * HK + h * EMB;
    __nv_bfloat16* Zl1 = g_Zlo + (size_t)r1 * HK + h * EMB;
#pragma unroll
    for (int j = 0; j < 16; j++) {
        int col = 8 * j + 2 * t4;
        float v00 = o[j][0] * rl0, v01 = o[j][1] * rl0;
        float v10 = o[j][2] * rl1, v11 = o[j][3] * rl1;
        __nv_bfloat16 h00, h01, h10, h11, l00, l01, l10, l11;
        split_bf(v00, h00, l00); split_bf(v01, h01, l01);
        split_bf(v10, h10, l10); split_bf(v11, h11, l11);
        *(uint32_t*)&Zh0[col] = pk(h00, h01);
        *(uint32_t*)&Zl0[col] = pk(l00, l01);
        *(uint32_t*)&Zh1[col] = pk(h10, h11);
        *(uint32_t*)&Zl1[col] = pk(l10, l11);
    }
}

// =======================================================================
// gemm_proj_mma: split-K proj on HMMA (2-stage, unchanged from R10).
// =======================================================================
__global__ __launch_bounds__(256, 1)
void gemm_proj_mma()
{
    extern __shared__ char smem[];
    const uint32_t sb = smem_u32(smem);
    const int tid = threadIdx.x, w = tid >> 5, lane = tid & 31;
    const int row0 = blockIdx.x * 128;
    const int ks   = blockIdx.y;
    const int wr = w >> 1, wc = w & 1;

    const __nv_bfloat16* zh = g_Zhi + (size_t)row0 * HK + ks * 256;
    const __nv_bfloat16* zl = g_Zlo + (size_t)row0 * HK + ks * 256;
    const __nv_bfloat16* ph = g_Phi + (size_t)ks * 256 * EMB;
    const __nv_bfloat16* pl = g_Plo + (size_t)ks * 256 * EMB;

    auto issue = [&](int kt) {
        uint32_t b = sb + (kt & 1) * QKV_BUF;
        int k0 = kt * 64;
#pragma unroll
        for (int t = 0; t < 4; t++) {
            int idx = tid + t * 256;
            int r = idx >> 3, s = idx & 7;
            uint32_t d = b + r * 144 + s * 16;
            cpa(d,         zh + r * HK + k0 + s * 8);
            cpa(d + XT_SZ, zl + r * HK + k0 + s * 8);
        }
#pragma unroll
        for (int t = 0; t < 4; t++) {
            int idx = tid + t * 256;
            int r = idx >> 4, s = idx & 15;
            uint32_t d = b + 2 * XT_SZ + r * 272 + s * 16;
            cpa(d,         ph + (k0 + r) * EMB + s * 8);
            cpa(d + WT_SZ, pl + (k0 + r) * EMB + s * 8);
        }
        CP_COMMIT();
    };
    issue(0); issue(1);

    float c[2][8][4];
#pragma unroll
    for (int rt = 0; rt < 2; rt++)
#pragma unroll
        for (int j = 0; j < 8; j++)
#pragma unroll
            for (int p = 0; p < 4; p++) c[rt][j][p] = 0.f;

    const int g = lane >> 2, t4 = lane & 3;
    const uint32_t a_off = (uint32_t)((wr * 32 + (lane & 15)) * 144 + (lane >> 4) * 16);
    const uint32_t b_off = (uint32_t)(2 * XT_SZ +
        (((lane >> 3) & 1) * 8 + (lane & 7)) * 272 + wc * 128 + (lane >> 4) * 16);

#pragma unroll 1
    for (int kt = 0; kt < 4; kt++) {
        if (kt < 3) asm volatile("cp.async.wait_group 1;");
        else        asm volatile("cp.async.wait_group 0;");
        __syncthreads();
        const uint32_t xb = sb + (kt & 1) * QKV_BUF;

#pragma unroll
        for (int kk = 0; kk < 4; kk++) {
            uint32_t ah[2][4], al[2][4];
#pragma unroll
            for (int rt = 0; rt < 2; rt++) {
                uint32_t aa = xb + a_off + rt * 16 * 144 + kk * 32;
                LDSM4(ah[rt], aa);
                LDSM4(al[rt], aa + XT_SZ);
            }
#pragma unroll
            for (int np = 0; np < 4; np++) {
                uint32_t ba = xb + b_off + kk * 16 * 272 + np * 32;
                uint32_t bh[4], bl[4];
                LDSM4T(bh, ba);
                LDSM4T(bl, ba + WT_SZ);
#pragma unroll
                for (int rt = 0; rt < 2; rt++) {
                    mma16816(c[rt][2 * np],     ah[rt], bh[0], bh[1]);
                    mma16816(c[rt][2 * np],     al[rt], bh[0], bh[1]);
                    mma16816(c[rt][2 * np],     ah[rt], bl[0], bl[1]);
                    mma16816(c[rt][2 * np + 1], ah[rt], bh[2], bh[3]);
                    mma16816(c[rt][2 * np + 1], al[rt], bh[2], bh[3]);
                    mma16816(c[rt][2 * np + 1], ah[rt], bl[2], bl[3]);
                }
            }
        }
        __syncthreads();
        if (kt + 2 < 4) issue(kt + 2);
    }

    float* Pp = g_Pp + (size_t)blockIdx.y * SEQ * EMB;
#pragma unroll
    for (int rt = 0; rt < 2; rt++) {
        const int r0 = row0 + wr * 32 + rt * 16 + g, r1 = r0 + 8;
#pragma unroll
        for (int j = 0; j < 8; j++) {
            int col = wc * 64 + 8 * j + 2 * t4;
            *(float2*)&Pp[r0 * EMB + col] = make_float2(c[rt][j][0], c[rt][j][1]);
            *(float2*)&Pp[r1 * EMB + col] = make_float2(c[rt][j][2], c[rt][j][3]);
        }
    }
}

__global__ __launch_bounds__(256)
void proj_reduce(float* __restrict__ out)
{
    int gid = blockIdx.x * 256 + threadIdx.x;
    const float4* p = (const float4*)g_Pp;
    const int STR = SEQ * EMB / 4;
    float4 s = p[gid];
#pragma unroll
    for (int z = 1; z < NSPLIT; z++) {
        float4 t = p[z * STR + gid];
        s.x += t.x; s.y += t.y; s.z += t.z; s.w += t.w;
    }
    ((float4*)out)[gid] = s;
}

// =======================================================================
extern "C" void kernel_launch(void* const* d_in, const int* in_sizes, int n_in,
                              void* d_out, int out_size)
{
    (void)in_sizes; (void)n_in; (void)out_size;
    const float* x    = (const float*)d_in[0];
    const float* Wq   = (const float*)d_in[1];
    const float* bq   = (const float*)d_in[2];
    const float* Wk   = (const float*)d_in[3];
    const float* bk   = (const float*)d_in[4];
    const float* Wv   = (const float*)d_in[5];
    const float* bv   = (const float*)d_in[6];
    const float* proj = (const float*)d_in[7];
    float* out = (float*)d_out;

    cudaFuncSetAttribute(gemm_qkv_mma,  cudaFuncAttributeMaxDynamicSharedMemorySize, QKV_SMEM3);
    cudaFuncSetAttribute(attn_mma,      cudaFuncAttributeMaxDynamicSharedMemorySize, ATT_SMEM);
    cudaFuncSetAttribute(gemm_proj_mma, cudaFuncAttributeMaxDynamicSharedMemorySize, PRJ_SMEM);

    conv_x<<<SEQ * WORD / 1024, 256>>>(x);
    conv_w<<<48 * WORD * EMB / 1024, 256>>>(Wq, Wk, Wv);
    conv_p<<<HK * EMB / 1024, 256>>>(proj);

    gemm_qkv_mma<<<dim3(SEQ / 128, 48), 256, QKV_SMEM3>>>(bq, bk, bv);

    attn_mma<<<dim3(SEQ / 128, NH), 256, ATT_SMEM>>>();

    gemm_proj_mma<<<dim3(SEQ / 128, NSPLIT), 256, PRJ_SMEM>>>();
    proj_reduce<<<SEQ * EMB / 1024, 256>>>(out);
}